// round 12
// baseline (speedup 1.0000x reference)
#include <cuda_runtime.h>
#include <cuda_bf16.h>
#include <math.h>
#include <stdint.h>

#define B_  2
#define S_  2048
#define E_  1024
#define H_  1024
#define NH_ 8
#define HD_ 128
#define L_  2
#define V_  32000
#define CS_ 128
#define NC_ 16
#define TOPK_ 8
#define R_  (B_ * S_)
#define FF_ (4 * H_)
#define HH_ (H_ / 2)
#define HS_ 3072
#define SCALE_ 0.08838834764831843f

// ---- scratch ----
__device__ __align__(16) float g_h  [R_ * H_];
__device__ __align__(16) float g_x  [R_ * H_];
__device__ __align__(16) float g_avg [B_ * NC_ * H_];
__device__ __align__(16) float g_cenc[B_ * NC_ * H_];
__device__ __align__(16) float g_qkvb[HS_];
__device__ unsigned g_sel[R_];
__device__ __align__(16) __nv_bfloat16 g_A0[R_ * FF_];
__device__ __align__(16) __nv_bfloat16 g_A1[R_ * FF_];
__device__ __align__(16) __nv_bfloat16 g_B0[R_ * FF_];
__device__ __align__(16) __nv_bfloat16 g_B1[R_ * FF_];
__device__ __align__(16) __nv_bfloat16 g_W0[32000 * 1024];
__device__ __align__(16) __nv_bfloat16 g_W1[32000 * 1024];
__device__ __align__(16) __nv_bfloat16 g_at0[R_ * HS_];
__device__ __align__(16) __nv_bfloat16 g_at1[R_ * HS_];

// ---- helpers ----
__device__ __forceinline__ float warpSum(float v) {
    #pragma unroll
    for (int o = 16; o > 0; o >>= 1) v += __shfl_xor_sync(0xffffffffu, v, o);
    return v;
}
__device__ __forceinline__ uint32_t smem_u32(const void* p) {
    uint32_t a;
    asm("{ .reg .u64 t; cvta.to.shared.u64 t, %1; cvt.u32.u64 %0, t; }" : "=r"(a) : "l"(p));
    return a;
}
#define CPA(d, s) asm volatile("cp.async.cg.shared.global [%0], [%1], 16;" :: "r"(d), "l"(s))
#define CPA_COMMIT() asm volatile("cp.async.commit_group;" ::: "memory")
#define CPA_WAIT0()  asm volatile("cp.async.wait_group 0;" ::: "memory")

#define LDSM_X4(r0, r1, r2, r3, a) \
    asm volatile("ldmatrix.sync.aligned.m8n8.x4.shared.b16 {%0,%1,%2,%3}, [%4];" \
        : "=r"(r0), "=r"(r1), "=r"(r2), "=r"(r3) : "r"(a))
#define LDSM_X4T(r0, r1, r2, r3, a) \
    asm volatile("ldmatrix.sync.aligned.m8n8.x4.trans.shared.b16 {%0,%1,%2,%3}, [%4];" \
        : "=r"(r0), "=r"(r1), "=r"(r2), "=r"(r3) : "r"(a))

#define MMA_BF16(c, a, b) \
    asm volatile("mma.sync.aligned.m16n8k16.row.col.f32.bf16.bf16.f32 " \
        "{%0,%1,%2,%3}, {%4,%5,%6,%7}, {%8,%9}, {%0,%1,%2,%3};" \
        : "+f"((c)[0]), "+f"((c)[1]), "+f"((c)[2]), "+f"((c)[3]) \
        : "r"((a)[0]), "r"((a)[1]), "r"((a)[2]), "r"((a)[3]), "r"((b)[0]), "r"((b)[1]))

__device__ __forceinline__ uint32_t packbf(float lo, float hi) {
    __nv_bfloat162 t = __floats2bfloat162_rn(lo, hi);
    return *(uint32_t*)&t;
}
__device__ __forceinline__ void split_store(__nv_bfloat16* o0, __nv_bfloat16* o1,
                                            size_t off, float vx, float vy) {
    float hx = __bfloat162float(__float2bfloat16_rn(vx));
    float hy = __bfloat162float(__float2bfloat16_rn(vy));
    *(uint32_t*)(o0 + off) = packbf(hx, hy);
    *(uint32_t*)(o1 + off) = packbf(vx - hx, vy - hy);
}

// ---- embedding (fused split output) ----
__global__ void embed_kernel(const int* __restrict__ ids, const float* __restrict__ tok,
                             const float* __restrict__ pos,
                             __nv_bfloat16* __restrict__ o0, __nv_bfloat16* __restrict__ o1) {
    int r = blockIdx.x;
    int id = ids[r];
    const float* t = tok + (size_t)id * E_;
    const float* p = pos + (size_t)(r % S_) * E_;
    size_t base = (size_t)r * E_;
    for (int e = threadIdx.x * 2; e < E_; e += blockDim.x * 2) {
        float vx = t[e] + p[e];
        float vy = t[e + 1] + p[e + 1];
        split_store(o0, o1, base + e, vx, vy);
    }
}

// ---- fp32 -> 2-way bf16 split ----
__global__ void cvt_split2_kernel(const float* __restrict__ a, __nv_bfloat16* __restrict__ o0,
                                  __nv_bfloat16* __restrict__ o1, int n) {
    int i = (blockIdx.x * blockDim.x + threadIdx.x) * 4;
    if (i >= n) return;
    float4 v = *(const float4*)(a + i);
    union { __nv_bfloat16 b[4]; uint2 u; } U0, U1;
    float f[4] = {v.x, v.y, v.z, v.w};
    #pragma unroll
    for (int j = 0; j < 4; j++) {
        __nv_bfloat16 b0 = __float2bfloat16_rn(f[j]);
        U0.b[j] = b0;
        U1.b[j] = __float2bfloat16_rn(f[j] - __bfloat162float(b0));
    }
    *(uint2*)(o0 + i) = U0.u;
    *(uint2*)(o1 + i) = U1.u;
}

// ---- fp32 W[K,N] -> 2-way split W^T[N,K] ----
__global__ void cvt_t2_kernel(const float* __restrict__ w, __nv_bfloat16* __restrict__ o0,
                              __nv_bfloat16* __restrict__ o1, int Kd, int Nd) {
    __shared__ float t[32][33];
    int n0 = blockIdx.x * 32, k0 = blockIdx.y * 32;
    int tx = threadIdx.x, ty = threadIdx.y;
    #pragma unroll
    for (int i = 0; i < 32; i += 8)
        t[ty + i][tx] = w[(size_t)(k0 + ty + i) * Nd + n0 + tx];
    __syncthreads();
    #pragma unroll
    for (int i = 0; i < 32; i += 8) {
        float v = t[tx][ty + i];
        __nv_bfloat16 b0 = __float2bfloat16_rn(v);
        size_t o = (size_t)(n0 + ty + i) * Kd + k0 + tx;
        o0[o] = b0;
        o1[o] = __float2bfloat16_rn(v - __bfloat162float(b0));
    }
}

// ---- HMMA split-bf16 GEMM (BK=64, 2-stage, 512 threads, warp tile 32x64) ----
// Grid: (M-blocks, N-strips) — x-fastest rasterization shares each B strip
// across all concurrent M-blocks (key for the N=32000 logits GEMM: B streamed
// once from DRAM instead of once per M-row).
#define SK 72
#define A_MAT (128 * SK * 2)
#define B_MAT (256 * SK * 2)
#define STG (2 * A_MAT + 2 * B_MAT)
#define GSMEM (2 * STG)

template<int NP>
__global__ void __launch_bounds__(512)
gemm_tc_kernel(const __nv_bfloat16* __restrict__ A0, const __nv_bfloat16* __restrict__ A1,
               const __nv_bfloat16* __restrict__ B0, const __nv_bfloat16* __restrict__ B1,
               const float* __restrict__ bias, const float* __restrict__ res,
               float* __restrict__ C, __nv_bfloat16* __restrict__ o0,
               __nv_bfloat16* __restrict__ o1, int M, int K, int N, int act) {
    extern __shared__ char smem[];
    const uint32_t sb = smem_u32(smem);
    const int tid = threadIdx.x, lane = tid & 31;
    const int w = tid >> 5, wm = w >> 2, wn = w & 3;
    const int m0 = blockIdx.x * 128, n0 = blockIdx.y * 256;

    float c[2][8][4];
    #pragma unroll
    for (int i = 0; i < 2; i++)
        #pragma unroll
        for (int j = 0; j < 8; j++)
            #pragma unroll
            for (int e = 0; e < 4; e++) c[i][j][e] = 0.f;

    const int arow = tid >> 3, aseg = tid & 7;
    int agrow_t = (m0 + arow < M) ? (m0 + arow) : (M - 1);
    const int arow2 = (tid + 512) >> 3, aseg2 = (tid + 512) & 7;
    int agrow2_t = (m0 + arow2 < M) ? (m0 + arow2) : (M - 1);

    auto issue_stage = [&](int kb, int st) {
        size_t gk = (size_t)kb * 64;
        uint32_t stb = sb + st * STG;
        {
            uint32_t d = stb + (arow * SK + aseg * 8) * 2;
            size_t o = (size_t)agrow_t * K + gk + aseg * 8;
            CPA(d, A0 + o);
            CPA(d + A_MAT, A1 + o);
            uint32_t d2 = stb + (arow2 * SK + aseg2 * 8) * 2;
            size_t o2 = (size_t)agrow2_t * K + gk + aseg2 * 8;
            CPA(d2, A0 + o2);
            CPA(d2 + A_MAT, A1 + o2);
        }
        #pragma unroll
        for (int i = 0; i < 4; i++) {
            int idx = tid + i * 512;
            int r = idx >> 3, sg = idx & 7;
            uint32_t d = stb + 2 * A_MAT + (r * SK + sg * 8) * 2;
            size_t o = (size_t)(n0 + r) * K + gk + sg * 8;
            CPA(d, B0 + o);
            CPA(d + B_MAT, B1 + o);
        }
        CPA_COMMIT();
    };

    const int nkb = K >> 6;
    issue_stage(0, 0);

    const uint32_t a_off = ((wm * 32 + (lane & 15)) * SK + ((lane >> 4) << 3)) * 2;
    const uint32_t b_off = ((wn * 64 + (lane & 7) + ((lane >> 4) << 3)) * SK + (((lane >> 3) & 1) << 3)) * 2;
    const int pa[4] = {0, 0, 1, 1};
    const int pb[4] = {0, 1, 0, 1};

    for (int kb = 0; kb < nkb; kb++) {
        CPA_WAIT0();
        __syncthreads();
        if (kb + 1 < nkb) issue_stage(kb + 1, (kb + 1) & 1);
        uint32_t base = sb + (kb & 1) * STG;
        #pragma unroll
        for (int kk = 0; kk < 4; kk++) {
            uint32_t af[2][2][4];
            #pragma unroll
            for (int s = 0; s < 2; s++)
                #pragma unroll
                for (int mt = 0; mt < 2; mt++) {
                    uint32_t ad = base + s * A_MAT + a_off + kk * 32 + mt * 16 * SK * 2;
                    LDSM_X4(af[s][mt][0], af[s][mt][1], af[s][mt][2], af[s][mt][3], ad);
                }
            uint32_t bf[2][2][4];
            #pragma unroll
            for (int s = 0; s < 2; s++) {
                uint32_t bd = base + 2 * A_MAT + s * B_MAT + b_off + kk * 32;
                LDSM_X4(bf[0][s][0], bf[0][s][1], bf[0][s][2], bf[0][s][3], bd);
            }
            #pragma unroll
            for (int nt2 = 0; nt2 < 4; nt2++) {
                int cur = nt2 & 1, nxt = cur ^ 1;
                if (nt2 < 3) {
                    #pragma unroll
                    for (int s = 0; s < 2; s++) {
                        uint32_t bd = base + 2 * A_MAT + s * B_MAT + b_off + kk * 32 + (nt2 + 1) * 16 * SK * 2;
                        LDSM_X4(bf[nxt][s][0], bf[nxt][s][1], bf[nxt][s][2], bf[nxt][s][3], bd);
                    }
                }
                #pragma unroll
                for (int p = 0; p < NP; p++)
                    #pragma unroll
                    for (int mt = 0; mt < 2; mt++)
                        #pragma unroll
                        for (int half = 0; half < 2; half++)
                            MMA_BF16(c[mt][nt2 * 2 + half], af[pa[p]][mt], bf[cur][pb[p]] + half * 2);
            }
        }
    }

    const int grp = lane >> 2, tig = lane & 3;
    #pragma unroll
    for (int mt = 0; mt < 2; mt++) {
        #pragma unroll
        for (int nt = 0; nt < 8; nt++) {
            int col = n0 + wn * 64 + nt * 8 + tig * 2;
            float b0 = bias[col], b1 = bias[col + 1];
            #pragma unroll
            for (int hrow = 0; hrow < 2; hrow++) {
                int row = m0 + wm * 32 + mt * 16 + grp + hrow * 8;
                if (row >= M) continue;
                float vx = c[mt][nt][hrow * 2 + 0] + b0;
                float vy = c[mt][nt][hrow * 2 + 1] + b1;
                if (act == 1) {
                    vx = fmaxf(vx, 0.f); vy = fmaxf(vy, 0.f);
                } else if (act == 2) {
                    vx = 0.5f * vx * (1.f + erff(vx * 0.7071067811865475f));
                    vy = 0.5f * vy * (1.f + erff(vy * 0.7071067811865475f));
                }
                size_t off = (size_t)row * N + col;
                if (o0) {
                    split_store(o0, o1, off, vx, vy);
                } else {
                    if (res) {
                        float2 r = *(const float2*)(res + off);
                        vx += r.x; vy += r.y;
                    }
                    float2 o; o.x = vx; o.y = vy;
                    *(float2*)(C + off) = o;
                }
            }
        }
    }
}

// ---- chunk mean (parallel over 4 dim groups) ----
__global__ void chunk_avg_kernel(const float* __restrict__ h, const int* __restrict__ ids,
                                 float* __restrict__ avg) {
    int c = blockIdx.x, b = blockIdx.y, dg = blockIdx.z;
    __shared__ float msk[CS_];
    __shared__ float s_cnt;
    int tid = threadIdx.x;
    if (tid < CS_) msk[tid] = (ids[b * S_ + c * CS_ + tid] != 0) ? 1.f : 0.f;
    __syncthreads();
    if (tid == 0) {
        float cn = 0.f;
        for (int p = 0; p < CS_; p++) cn += msk[p];
        s_cnt = cn;
    }
    __syncthreads();
    float inv = 1.f / (s_cnt + 1e-10f);
    int d = dg * 256 + tid;
    float s = 0.f;
    for (int p = 0; p < CS_; p++)
        s += h[(size_t)(b * S_ + c * CS_ + p) * H_ + d] * msk[p];
    avg[(size_t)(b * NC_ + c) * H_ + d] = s * inv;
}

// ---- topk ----
__global__ void __launch_bounds__(512)
topk_kernel(const float* __restrict__ qe, const float* __restrict__ cenc,
            unsigned* __restrict__ sel) {
    int s = blockIdx.x, b = blockIdx.y;
    int tid = threadIdx.x, warp = tid >> 5, lane = tid & 31;
    __shared__ float sc[NC_];
    const float* q = qe + (size_t)(b * S_ + s) * H_;
    const float* c = cenc + (size_t)(b * NC_ + warp) * H_;
    float d = 0.f;
    for (int e = lane; e < H_; e += 32) d += q[e] * c[e];
    d = warpSum(d);
    if (lane == 0) sc[warp] = d;
    __syncthreads();
    if (tid == 0) {
        unsigned chosen = 0;
        for (int t = 0; t < TOPK_; t++) {
            float best = -INFINITY;
            int bi = 0;
            for (int cc = 0; cc < NC_; cc++)
                if (!((chosen >> cc) & 1u) && sc[cc] > best) { best = sc[cc]; bi = cc; }
            chosen |= 1u << bi;
        }
        sel[b * S_ + s] = chosen;
    }
}

// ---- LayerNorm (fused split output) ----
__global__ void ln_kernel(const float* __restrict__ x, const float* __restrict__ g,
                          const float* __restrict__ bt,
                          __nv_bfloat16* __restrict__ o0, __nv_bfloat16* __restrict__ o1) {
    int r = blockIdx.x;
    int tid = threadIdx.x, warp = tid >> 5, lane = tid & 31;
    const float* xr = x + (size_t)r * H_;
    float s = 0.f, sq = 0.f;
    for (int e = tid; e < H_; e += 256) {
        float v = xr[e];
        s += v; sq += v * v;
    }
    __shared__ float rs[8], rq[8];
    __shared__ float s_mean, s_rstd;
    s = warpSum(s); sq = warpSum(sq);
    if (lane == 0) { rs[warp] = s; rq[warp] = sq; }
    __syncthreads();
    if (tid == 0) {
        float Sm = 0.f, Q = 0.f;
        for (int ww = 0; ww < 8; ww++) { Sm += rs[ww]; Q += rq[ww]; }
        float mean = Sm / (float)H_;
        float var = Q / (float)H_ - mean * mean;
        s_mean = mean;
        s_rstd = rsqrtf(var + 1e-5f);
    }
    __syncthreads();
    float mean = s_mean, rstd = s_rstd;
    size_t base = (size_t)r * H_;
    for (int e = tid * 2; e < H_; e += 512) {
        float vx = (xr[e] - mean) * rstd * g[e] + bt[e];
        float vy = (xr[e + 1] - mean) * rstd * g[e + 1] + bt[e + 1];
        split_store(o0, o1, base + e, vx, vy);
    }
}

// ---- HMMA sparse chunk attention: 32 queries/block (2x16 groups share K/V) ----
#define AST 136
#define KOFF0 0
#define KOFF1 34816
#define VOFF0 69632
#define VOFF1 104448
#define QOFF0 139264
#define QOFF1 147968
#define NOFF  156672
#define DOFF  173056
#define ASMEM 173184

__global__ void __launch_bounds__(256)
attn_kernel(const __nv_bfloat16* __restrict__ qkv0, const __nv_bfloat16* __restrict__ qkv1,
            const unsigned* __restrict__ sel,
            __nv_bfloat16* __restrict__ out0, __nv_bfloat16* __restrict__ out1) {
    extern __shared__ char sm[];
    const uint32_t sb = smem_u32(sm);
    const int tid = threadIdx.x, lane = tid & 31;
    const int w = tid >> 5, gq = w >> 2, wq = w & 3;
    const int g_tid = tid & 127;
    const int head = blockIdx.y, b = blockIdx.z;
    const int s0 = blockIdx.x * 32;
    float* num = (float*)(sm + NOFF);
    float* den = (float*)(sm + DOFF);
    __shared__ unsigned smask[32];
    __shared__ unsigned s_union;

    for (int i = tid; i < 32 * 128; i += 256) num[i] = 0.f;
    if (tid < 32) { smask[tid] = sel[b * S_ + s0 + tid]; den[tid] = 0.f; }
    __syncthreads();
    if (tid == 0) {
        unsigned u = 0;
        for (int i = 0; i < 32; i++) u |= smask[i];
        s_union = u;
    }
    {
        int row = tid >> 3, sp = tid & 7;
        size_t src = ((size_t)(b * S_ + s0 + row)) * HS_ + head * HD_ + sp * 16;
        int gg = row >> 4, lrow = row & 15;
        uint32_t d = gg * 4352 + lrow * (AST * 2) + sp * 32;
        CPA(sb + QOFF0 + d,      qkv0 + src);
        CPA(sb + QOFF0 + d + 16, qkv0 + src + 8);
        CPA(sb + QOFF1 + d,      qkv1 + src);
        CPA(sb + QOFF1 + d + 16, qkv1 + src + 8);
    }
    CPA_COMMIT();
    CPA_WAIT0();
    __syncthreads();

    uint32_t qf[2][8][4];
    const uint32_t qa = gq * 4352 + (lane & 15) * (AST * 2) + ((lane >> 4) << 4);
    #pragma unroll
    for (int s = 0; s < 2; s++)
        #pragma unroll
        for (int ks = 0; ks < 8; ks++) {
            uint32_t ad = sb + (s ? QOFF1 : QOFF0) + qa + ks * 32;
            LDSM_X4(qf[s][ks][0], qf[s][ks][1], qf[s][ks][2], qf[s][ks][3], ad);
        }

    float oacc[16][4];
    #pragma unroll
    for (int t = 0; t < 16; t++)
        #pragma unroll
        for (int e = 0; e < 4; e++) oacc[t][e] = 0.f;

    const unsigned um = s_union;
    const int r0 = lane >> 2, r1 = r0 + 8;
    const uint32_t kb_off = (wq * 32 + (lane & 7) + ((lane >> 4) << 3)) * (AST * 2) + (((lane >> 3) & 1) << 4);
    const uint32_t vb_off = (wq * 32 + (lane & 15)) * (AST * 2) + ((lane >> 4) << 4);

    for (int c = 0; c < NC_; c++) {
        if (!((um >> c) & 1u)) continue;
        int j0 = c * CS_;
        {
            int row = tid >> 1, hf = tid & 1;
            size_t src = ((size_t)(b * S_ + j0 + row)) * HS_ + head * HD_ + hf * 64;
            uint32_t d = row * (AST * 2) + hf * 128;
            const __nv_bfloat16* k0p = qkv0 + 1024;
            const __nv_bfloat16* k1p = qkv1 + 1024;
            const __nv_bfloat16* v0p = qkv0 + 2048;
            const __nv_bfloat16* v1p = qkv1 + 2048;
            #pragma unroll
            for (int g = 0; g < 8; g++) {
                CPA(sb + KOFF0 + d + g * 16, k0p + src + g * 8);
                CPA(sb + KOFF1 + d + g * 16, k1p + src + g * 8);
                CPA(sb + VOFF0 + d + g * 16, v0p + src + g * 8);
                CPA(sb + VOFF1 + d + g * 16, v1p + src + g * 8);
            }
        }
        CPA_COMMIT();
        CPA_WAIT0();
        __syncthreads();

        float sc[4][4];
        #pragma unroll
        for (int t = 0; t < 4; t++)
            #pragma unroll
            for (int e = 0; e < 4; e++) sc[t][e] = 0.f;
        #pragma unroll
        for (int ks = 0; ks < 8; ks++) {
            uint32_t kfA0[4], kfA1[4], kfB0[4], kfB1[4];
            LDSM_X4(kfA0[0], kfA0[1], kfA0[2], kfA0[3], sb + KOFF0 + kb_off + ks * 32);
            LDSM_X4(kfB0[0], kfB0[1], kfB0[2], kfB0[3], sb + KOFF0 + kb_off + 16 * AST * 2 + ks * 32);
            LDSM_X4(kfA1[0], kfA1[1], kfA1[2], kfA1[3], sb + KOFF1 + kb_off + ks * 32);
            LDSM_X4(kfB1[0], kfB1[1], kfB1[2], kfB1[3], sb + KOFF1 + kb_off + 16 * AST * 2 + ks * 32);
            #pragma unroll
            for (int qs = 0; qs < 2; qs++) {
                uint32_t* a = qf[qs][ks];
                MMA_BF16(sc[0], a, kfA0 + 0); MMA_BF16(sc[1], a, kfA0 + 2);
                MMA_BF16(sc[2], a, kfB0 + 0); MMA_BF16(sc[3], a, kfB0 + 2);
                MMA_BF16(sc[0], a, kfA1 + 0); MMA_BF16(sc[1], a, kfA1 + 2);
                MMA_BF16(sc[2], a, kfB1 + 0); MMA_BF16(sc[3], a, kfB1 + 2);
            }
        }
        bool m0 = (smask[gq * 16 + r0] >> c) & 1u, m1 = (smask[gq * 16 + r1] >> c) & 1u;
        float d0 = 0.f, d1 = 0.f;
        uint32_t pf[2][2][4];
        #pragma unroll
        for (int t = 0; t < 4; t++) {
            float e0 = m0 ? expf(sc[t][0] * SCALE_) : 0.f;
            float e1 = m0 ? expf(sc[t][1] * SCALE_) : 0.f;
            float e2 = m1 ? expf(sc[t][2] * SCALE_) : 0.f;
            float e3 = m1 ? expf(sc[t][3] * SCALE_) : 0.f;
            d0 += e0 + e1; d1 += e2 + e3;
            float h0 = __bfloat162float(__float2bfloat16_rn(e0));
            float h1 = __bfloat162float(__float2bfloat16_rn(e1));
            float h2 = __bfloat162float(__float2bfloat16_rn(e2));
            float h3 = __bfloat162float(__float2bfloat16_rn(e3));
            int g = t >> 1, o = (t & 1) * 2;
            pf[g][0][o + 0] = packbf(h0, h1);
            pf[g][0][o + 1] = packbf(h2, h3);
            pf[g][1][o + 0] = packbf(e0 - h0, e1 - h1);
            pf[g][1][o + 1] = packbf(e2 - h2, e3 - h3);
        }
        d0 += __shfl_xor_sync(0xffffffffu, d0, 1);
        d0 += __shfl_xor_sync(0xffffffffu, d0, 2);
        d1 += __shfl_xor_sync(0xffffffffu, d1, 1);
        d1 += __shfl_xor_sync(0xffffffffu, d1, 2);
        if ((lane & 3) == 0) {
            atomicAdd(&den[gq * 16 + r0], d0);
            atomicAdd(&den[gq * 16 + r1], d1);
        }
        #pragma unroll
        for (int dg = 0; dg < 8; dg++) {
            #pragma unroll
            for (int kg = 0; kg < 2; kg++) {
                uint32_t vf0[4], vf1[4];
                LDSM_X4T(vf0[0], vf0[1], vf0[2], vf0[3], sb + VOFF0 + vb_off + kg * 16 * AST * 2 + dg * 32);
                LDSM_X4T(vf1[0], vf1[1], vf1[2], vf1[3], sb + VOFF1 + vb_off + kg * 16 * AST * 2 + dg * 32);
                #pragma unroll
                for (int ps = 0; ps < 2; ps++) {
                    uint32_t* a = pf[kg][ps];
                    MMA_BF16(oacc[2 * dg + 0], a, vf0 + 0);
                    MMA_BF16(oacc[2 * dg + 1], a, vf0 + 2);
                    MMA_BF16(oacc[2 * dg + 0], a, vf1 + 0);
                    MMA_BF16(oacc[2 * dg + 1], a, vf1 + 2);
                }
            }
        }
        __syncthreads();
    }

    for (int ww = 0; ww < 4; ww++) {
        if (wq == ww) {
            #pragma unroll
            for (int t = 0; t < 16; t++) {
                int dbase = 8 * t + 2 * (lane & 3);
                int rb = gq * 16;
                num[(rb + r0) * 128 + dbase + 0] += oacc[t][0];
                num[(rb + r0) * 128 + dbase + 1] += oacc[t][1];
                num[(rb + r1) * 128 + dbase + 0] += oacc[t][2];
                num[(rb + r1) * 128 + dbase + 1] += oacc[t][3];
            }
        }
        __syncthreads();
    }
    for (int r = 0; r < 16; r += 2) {
        int rr = r + (g_tid >> 6);
        int e = (g_tid & 63) * 2;
        int qrow = gq * 16 + rr;
        float dv = den[qrow];
        float vx = num[qrow * 128 + e] / dv;
        float vy = num[qrow * 128 + e + 1] / dv;
        split_store(out0, out1, ((size_t)(b * S_ + s0 + qrow)) * H_ + head * HD_ + e, vx, vy);
    }
}

// ---- host ----
static __nv_bfloat16 *s_A0, *s_A1, *s_B0, *s_B1, *s_W0, *s_W1, *s_at0, *s_at1;
static float* s_qkvb;

static inline void cvt2(const float* A, __nv_bfloat16* d0, __nv_bfloat16* d1, int n) {
    cvt_split2_kernel<<<(n / 4 + 255) / 256, 256>>>(A, d0, d1, n);
}
static inline void gemm_go(const __nv_bfloat16* A0, const __nv_bfloat16* A1,
                           const float* bias, const float* res,
                           float* C, __nv_bfloat16* o0, __nv_bfloat16* o1,
                           int M, int K, int N, int act, int hi) {
    dim3 grid((M + 127) / 128, N / 256);
    if (hi)
        gemm_tc_kernel<4><<<grid, 512, GSMEM>>>(A0, A1, s_W0, s_W1, bias, res, C, o0, o1, M, K, N, act);
    else
        gemm_tc_kernel<3><<<grid, 512, GSMEM>>>(A0, A1, s_W0, s_W1, bias, res, C, o0, o1, M, K, N, act);
}
static inline void run_gemm(const __nv_bfloat16* A0, const __nv_bfloat16* A1,
                            const float* W, const float* bias, const float* res,
                            float* C, __nv_bfloat16* o0, __nv_bfloat16* o1,
                            int M, int K, int N, int act, int hi) {
    cvt_t2_kernel<<<dim3(N / 32, K / 32), dim3(32, 8)>>>(W, s_W0, s_W1, K, N);
    gemm_go(A0, A1, bias, res, C, o0, o1, M, K, N, act, hi);
}

extern "C" void kernel_launch(void* const* d_in, const int* in_sizes, int n_in,
                              void* d_out, int out_size) {
    const int*   ids     = (const int*)  d_in[0];
    const float* tok_emb = (const float*)d_in[1];
    const float* pos_emb = (const float*)d_in[2];
    const float* in_w    = (const float*)d_in[3];
    const float* in_b    = (const float*)d_in[4];
    const float* ch_w1   = (const float*)d_in[5];
    const float* ch_b1   = (const float*)d_in[6];
    const float* ch_w2   = (const float*)d_in[7];
    const float* ch_b2   = (const float*)d_in[8];
    const float* qe_w1   = (const float*)d_in[9];
    const float* qe_b1   = (const float*)d_in[10];
    const float* qe_w2   = (const float*)d_in[11];
    const float* qe_b2   = (const float*)d_in[12];
    const float* q_w     = (const float*)d_in[13];
    const float* q_b     = (const float*)d_in[14];
    const float* k_w     = (const float*)d_in[15];
    const float* k_b     = (const float*)d_in[16];
    const float* v_w     = (const float*)d_in[17];
    const float* v_b     = (const float*)d_in[18];
    const float* o_w     = (const float*)d_in[19];
    const float* o_b     = (const float*)d_in[20];
    const float* f_w1    = (const float*)d_in[21];
    const float* f_b1    = (const float*)d_in[22];
    const float* f_w2    = (const float*)d_in[23];
    const float* f_b2    = (const float*)d_in[24];
    const float* ln1_g   = (const float*)d_in[25];
    const float* ln1_b   = (const float*)d_in[26];
    const float* ln2_g   = (const float*)d_in[27];
    const float* ln2_b   = (const float*)d_in[28];
    const float* out_w   = (const float*)d_in[29];
    const float* out_b   = (const float*)d_in[30];
    float* logits = (float*)d_out;

    cudaFuncSetAttribute(gemm_tc_kernel<4>, cudaFuncAttributeMaxDynamicSharedMemorySize, GSMEM);
    cudaFuncSetAttribute(gemm_tc_kernel<3>, cudaFuncAttributeMaxDynamicSharedMemorySize, GSMEM);
    cudaFuncSetAttribute(attn_kernel, cudaFuncAttributeMaxDynamicSharedMemorySize, ASMEM);

    float *h, *x, *avg, *cenc;
    unsigned* sel;
    cudaGetSymbolAddress((void**)&h,    g_h);
    cudaGetSymbolAddress((void**)&x,    g_x);
    cudaGetSymbolAddress((void**)&avg,  g_avg);
    cudaGetSymbolAddress((void**)&cenc, g_cenc);
    cudaGetSymbolAddress((void**)&sel,  g_sel);
    cudaGetSymbolAddress((void**)&s_A0, g_A0);
    cudaGetSymbolAddress((void**)&s_A1, g_A1);
    cudaGetSymbolAddress((void**)&s_B0, g_B0);
    cudaGetSymbolAddress((void**)&s_B1, g_B1);
    cudaGetSymbolAddress((void**)&s_W0, g_W0);
    cudaGetSymbolAddress((void**)&s_W1, g_W1);
    cudaGetSymbolAddress((void**)&s_at0, g_at0);
    cudaGetSymbolAddress((void**)&s_at1, g_at1);
    cudaGetSymbolAddress((void**)&s_qkvb, g_qkvb);

    // embeddings (split) -> in-proj -> h (fp32)
    embed_kernel<<<R_, 256>>>(ids, tok_emb, pos_emb, s_A0, s_A1);
    run_gemm(s_A0, s_A1, in_w, in_b, nullptr, h, nullptr, nullptr, R_, E_, H_, 0, 1);

    // chunk encodings
    chunk_avg_kernel<<<dim3(NC_, B_, 4), 256>>>(h, ids, avg);
    cvt2(avg, s_A0, s_A1, B_ * NC_ * H_);
    run_gemm(s_A0, s_A1, ch_w1, ch_b1, nullptr, nullptr, s_B0, s_B1, B_ * NC_, H_, HH_, 1, 1);
    run_gemm(s_B0, s_B1, ch_w2, ch_b2, nullptr, cenc, nullptr, nullptr, B_ * NC_, HH_, H_, 0, 1);

    for (int i = 0; i < L_; i++) {
        // selection path (hi precision)
        cvt2(h, s_A0, s_A1, R_ * H_);
        run_gemm(s_A0, s_A1, qe_w1, qe_b1, nullptr, nullptr, s_B0, s_B1, R_, H_, HH_, 1, 1);
        run_gemm(s_B0, s_B1, qe_w2, qe_b2, nullptr, x, nullptr, nullptr, R_, HH_, H_, 0, 1);
        topk_kernel<<<dim3(S_, B_), 512>>>(x, cenc, sel);

        int hi = (i == 0) ? 1 : 0;
        ln_kernel<<<R_, 256>>>(h, ln1_g + i * H_, ln1_b + i * H_, s_A0, s_A1);
        // merged qkv: W^T rows [q | k | v], bias concatenated
        cvt_t2_kernel<<<dim3(32, 32), dim3(32, 8)>>>(q_w + (size_t)i * H_ * H_, s_W0, s_W1, H_, H_);
        cvt_t2_kernel<<<dim3(32, 32), dim3(32, 8)>>>(k_w + (size_t)i * H_ * H_,
            s_W0 + (size_t)H_ * H_, s_W1 + (size_t)H_ * H_, H_, H_);
        cvt_t2_kernel<<<dim3(32, 32), dim3(32, 8)>>>(v_w + (size_t)i * H_ * H_,
            s_W0 + (size_t)2 * H_ * H_, s_W1 + (size_t)2 * H_ * H_, H_, H_);
        cudaMemcpyAsync(s_qkvb,        q_b + i * H_, H_ * 4, cudaMemcpyDeviceToDevice);
        cudaMemcpyAsync(s_qkvb + H_,   k_b + i * H_, H_ * 4, cudaMemcpyDeviceToDevice);
        cudaMemcpyAsync(s_qkvb + 2*H_, v_b + i * H_, H_ * 4, cudaMemcpyDeviceToDevice);
        gemm_go(s_A0, s_A1, s_qkvb, nullptr, nullptr, s_at0, s_at1, R_, H_, HS_, 0, hi);

        attn_kernel<<<dim3(S_ / 32, NH_, B_), 256, ASMEM>>>(s_at0, s_at1, sel, s_B0, s_B1);
        run_gemm(s_B0, s_B1, o_w + (size_t)i * H_ * H_, o_b + i * H_, h, h, nullptr, nullptr,
                 R_, H_, H_, 0, hi);

        ln_kernel<<<R_, 256>>>(h, ln2_g + i * H_, ln2_b + i * H_, s_A0, s_A1);
        run_gemm(s_A0, s_A1, f_w1 + (size_t)i * H_ * FF_, f_b1 + i * FF_, nullptr, nullptr,
                 s_B0, s_B1, R_, H_, FF_, 2, hi);
        run_gemm(s_B0, s_B1, f_w2 + (size_t)i * FF_ * H_, f_b2 + i * H_, h, h, nullptr, nullptr,
                 R_, FF_, H_, 0, hi);
    }

    cvt2(h, s_A0, s_A1, R_ * H_);
    run_gemm(s_A0, s_A1, out_w, out_b, nullptr, logits, nullptr, nullptr, R_, H_, V_, 0, 0);
}

// round 13
// speedup vs baseline: 1.0059x; 1.0059x over previous
#include <cuda_runtime.h>
#include <cuda_bf16.h>
#include <math.h>
#include <stdint.h>

#define B_  2
#define S_  2048
#define E_  1024
#define H_  1024
#define NH_ 8
#define HD_ 128
#define L_  2
#define V_  32000
#define CS_ 128
#define NC_ 16
#define TOPK_ 8
#define R_  (B_ * S_)
#define FF_ (4 * H_)
#define HH_ (H_ / 2)
#define HS_ 3072
#define SCALE_ 0.08838834764831843f

// ---- scratch ----
__device__ __align__(16) float g_h  [R_ * H_];
__device__ __align__(16) float g_x  [R_ * H_];
__device__ __align__(16) float g_avg [B_ * NC_ * H_];
__device__ __align__(16) float g_cenc[B_ * NC_ * H_];
__device__ __align__(16) float g_qkvb[HS_];
__device__ unsigned g_sel[R_];
__device__ __align__(16) __nv_bfloat16 g_A0[R_ * FF_];
__device__ __align__(16) __nv_bfloat16 g_A1[R_ * FF_];
__device__ __align__(16) __nv_bfloat16 g_B0[R_ * FF_];
__device__ __align__(16) __nv_bfloat16 g_B1[R_ * FF_];
__device__ __align__(16) __nv_bfloat16 g_W0[32000 * 1024];
__device__ __align__(16) __nv_bfloat16 g_W1[32000 * 1024];
__device__ __align__(16) __nv_bfloat16 g_at0[R_ * HS_];
__device__ __align__(16) __nv_bfloat16 g_at1[R_ * HS_];

// ---- helpers ----
__device__ __forceinline__ float warpSum(float v) {
    #pragma unroll
    for (int o = 16; o > 0; o >>= 1) v += __shfl_xor_sync(0xffffffffu, v, o);
    return v;
}
__device__ __forceinline__ uint32_t smem_u32(const void* p) {
    uint32_t a;
    asm("{ .reg .u64 t; cvta.to.shared.u64 t, %1; cvt.u32.u64 %0, t; }" : "=r"(a) : "l"(p));
    return a;
}
#define CPA(d, s) asm volatile("cp.async.cg.shared.global [%0], [%1], 16;" :: "r"(d), "l"(s))
#define CPA_COMMIT() asm volatile("cp.async.commit_group;" ::: "memory")
#define CPA_WAIT0()  asm volatile("cp.async.wait_group 0;" ::: "memory")
#define CPA_WAIT1()  asm volatile("cp.async.wait_group 1;" ::: "memory")

#define LDSM_X4(r0, r1, r2, r3, a) \
    asm volatile("ldmatrix.sync.aligned.m8n8.x4.shared.b16 {%0,%1,%2,%3}, [%4];" \
        : "=r"(r0), "=r"(r1), "=r"(r2), "=r"(r3) : "r"(a))
#define LDSM_X4T(r0, r1, r2, r3, a) \
    asm volatile("ldmatrix.sync.aligned.m8n8.x4.trans.shared.b16 {%0,%1,%2,%3}, [%4];" \
        : "=r"(r0), "=r"(r1), "=r"(r2), "=r"(r3) : "r"(a))

#define MMA_BF16(c, a, b) \
    asm volatile("mma.sync.aligned.m16n8k16.row.col.f32.bf16.bf16.f32 " \
        "{%0,%1,%2,%3}, {%4,%5,%6,%7}, {%8,%9}, {%0,%1,%2,%3};" \
        : "+f"((c)[0]), "+f"((c)[1]), "+f"((c)[2]), "+f"((c)[3]) \
        : "r"((a)[0]), "r"((a)[1]), "r"((a)[2]), "r"((a)[3]), "r"((b)[0]), "r"((b)[1]))

__device__ __forceinline__ uint32_t packbf(float lo, float hi) {
    __nv_bfloat162 t = __floats2bfloat162_rn(lo, hi);
    return *(uint32_t*)&t;
}
__device__ __forceinline__ void split_store(__nv_bfloat16* o0, __nv_bfloat16* o1,
                                            size_t off, float vx, float vy) {
    float hx = __bfloat162float(__float2bfloat16_rn(vx));
    float hy = __bfloat162float(__float2bfloat16_rn(vy));
    *(uint32_t*)(o0 + off) = packbf(hx, hy);
    *(uint32_t*)(o1 + off) = packbf(vx - hx, vy - hy);
}

// ---- embedding (fused split output) ----
__global__ void embed_kernel(const int* __restrict__ ids, const float* __restrict__ tok,
                             const float* __restrict__ pos,
                             __nv_bfloat16* __restrict__ o0, __nv_bfloat16* __restrict__ o1) {
    int r = blockIdx.x;
    int id = ids[r];
    const float* t = tok + (size_t)id * E_;
    const float* p = pos + (size_t)(r % S_) * E_;
    size_t base = (size_t)r * E_;
    for (int e = threadIdx.x * 2; e < E_; e += blockDim.x * 2) {
        float vx = t[e] + p[e];
        float vy = t[e + 1] + p[e + 1];
        split_store(o0, o1, base + e, vx, vy);
    }
}

// ---- fp32 -> 2-way bf16 split ----
__global__ void cvt_split2_kernel(const float* __restrict__ a, __nv_bfloat16* __restrict__ o0,
                                  __nv_bfloat16* __restrict__ o1, int n) {
    int i = (blockIdx.x * blockDim.x + threadIdx.x) * 4;
    if (i >= n) return;
    float4 v = *(const float4*)(a + i);
    union { __nv_bfloat16 b[4]; uint2 u; } U0, U1;
    float f[4] = {v.x, v.y, v.z, v.w};
    #pragma unroll
    for (int j = 0; j < 4; j++) {
        __nv_bfloat16 b0 = __float2bfloat16_rn(f[j]);
        U0.b[j] = b0;
        U1.b[j] = __float2bfloat16_rn(f[j] - __bfloat162float(b0));
    }
    *(uint2*)(o0 + i) = U0.u;
    *(uint2*)(o1 + i) = U1.u;
}

// ---- fp32 W[K,N] -> 2-way split W^T[N,K] ----
__global__ void cvt_t2_kernel(const float* __restrict__ w, __nv_bfloat16* __restrict__ o0,
                              __nv_bfloat16* __restrict__ o1, int Kd, int Nd) {
    __shared__ float t[32][33];
    int n0 = blockIdx.x * 32, k0 = blockIdx.y * 32;
    int tx = threadIdx.x, ty = threadIdx.y;
    #pragma unroll
    for (int i = 0; i < 32; i += 8)
        t[ty + i][tx] = w[(size_t)(k0 + ty + i) * Nd + n0 + tx];
    __syncthreads();
    #pragma unroll
    for (int i = 0; i < 32; i += 8) {
        float v = t[tx][ty + i];
        __nv_bfloat16 b0 = __float2bfloat16_rn(v);
        size_t o = (size_t)(n0 + ty + i) * Kd + k0 + tx;
        o0[o] = b0;
        o1[o] = __float2bfloat16_rn(v - __bfloat162float(b0));
    }
}

// ---- HMMA split-bf16 GEMM (BK=64, 2-stage, 512 threads, warp tile 32x64) ----
#define SK 72
#define A_MAT (128 * SK * 2)
#define B_MAT (256 * SK * 2)
#define STG (2 * A_MAT + 2 * B_MAT)
#define GSMEM (2 * STG)

template<int NP>
__global__ void __launch_bounds__(512)
gemm_tc_kernel(const __nv_bfloat16* __restrict__ A0, const __nv_bfloat16* __restrict__ A1,
               const __nv_bfloat16* __restrict__ B0, const __nv_bfloat16* __restrict__ B1,
               const float* __restrict__ bias, const float* __restrict__ res,
               float* __restrict__ C, __nv_bfloat16* __restrict__ o0,
               __nv_bfloat16* __restrict__ o1, int M, int K, int N, int act) {
    extern __shared__ char smem[];
    const uint32_t sb = smem_u32(smem);
    const int tid = threadIdx.x, lane = tid & 31;
    const int w = tid >> 5, wm = w >> 2, wn = w & 3;
    const int m0 = blockIdx.y * 128, n0 = blockIdx.x * 256;

    float c[2][8][4];
    #pragma unroll
    for (int i = 0; i < 2; i++)
        #pragma unroll
        for (int j = 0; j < 8; j++)
            #pragma unroll
            for (int e = 0; e < 4; e++) c[i][j][e] = 0.f;

    const int arow = tid >> 3, aseg = tid & 7;
    int agrow_t = (m0 + arow < M) ? (m0 + arow) : (M - 1);
    const int arow2 = (tid + 512) >> 3, aseg2 = (tid + 512) & 7;
    int agrow2_t = (m0 + arow2 < M) ? (m0 + arow2) : (M - 1);

    auto issue_stage = [&](int kb, int st) {
        size_t gk = (size_t)kb * 64;
        uint32_t stb = sb + st * STG;
        {
            uint32_t d = stb + (arow * SK + aseg * 8) * 2;
            size_t o = (size_t)agrow_t * K + gk + aseg * 8;
            CPA(d, A0 + o);
            CPA(d + A_MAT, A1 + o);
            uint32_t d2 = stb + (arow2 * SK + aseg2 * 8) * 2;
            size_t o2 = (size_t)agrow2_t * K + gk + aseg2 * 8;
            CPA(d2, A0 + o2);
            CPA(d2 + A_MAT, A1 + o2);
        }
        #pragma unroll
        for (int i = 0; i < 4; i++) {
            int idx = tid + i * 512;
            int r = idx >> 3, sg = idx & 7;
            uint32_t d = stb + 2 * A_MAT + (r * SK + sg * 8) * 2;
            size_t o = (size_t)(n0 + r) * K + gk + sg * 8;
            CPA(d, B0 + o);
            CPA(d + B_MAT, B1 + o);
        }
        CPA_COMMIT();
    };

    const int nkb = K >> 6;
    issue_stage(0, 0);

    const uint32_t a_off = ((wm * 32 + (lane & 15)) * SK + ((lane >> 4) << 3)) * 2;
    const uint32_t b_off = ((wn * 64 + (lane & 7) + ((lane >> 4) << 3)) * SK + (((lane >> 3) & 1) << 3)) * 2;
    const int pa[4] = {0, 0, 1, 1};
    const int pb[4] = {0, 1, 0, 1};

    for (int kb = 0; kb < nkb; kb++) {
        CPA_WAIT0();
        __syncthreads();
        if (kb + 1 < nkb) issue_stage(kb + 1, (kb + 1) & 1);
        uint32_t base = sb + (kb & 1) * STG;
        #pragma unroll
        for (int kk = 0; kk < 4; kk++) {
            uint32_t af[2][2][4];
            #pragma unroll
            for (int s = 0; s < 2; s++)
                #pragma unroll
                for (int mt = 0; mt < 2; mt++) {
                    uint32_t ad = base + s * A_MAT + a_off + kk * 32 + mt * 16 * SK * 2;
                    LDSM_X4(af[s][mt][0], af[s][mt][1], af[s][mt][2], af[s][mt][3], ad);
                }
            uint32_t bf[2][2][4];
            #pragma unroll
            for (int s = 0; s < 2; s++) {
                uint32_t bd = base + 2 * A_MAT + s * B_MAT + b_off + kk * 32;
                LDSM_X4(bf[0][s][0], bf[0][s][1], bf[0][s][2], bf[0][s][3], bd);
            }
            #pragma unroll
            for (int nt2 = 0; nt2 < 4; nt2++) {
                int cur = nt2 & 1, nxt = cur ^ 1;
                if (nt2 < 3) {
                    #pragma unroll
                    for (int s = 0; s < 2; s++) {
                        uint32_t bd = base + 2 * A_MAT + s * B_MAT + b_off + kk * 32 + (nt2 + 1) * 16 * SK * 2;
                        LDSM_X4(bf[nxt][s][0], bf[nxt][s][1], bf[nxt][s][2], bf[nxt][s][3], bd);
                    }
                }
                #pragma unroll
                for (int p = 0; p < NP; p++)
                    #pragma unroll
                    for (int mt = 0; mt < 2; mt++)
                        #pragma unroll
                        for (int half = 0; half < 2; half++)
                            MMA_BF16(c[mt][nt2 * 2 + half], af[pa[p]][mt], bf[cur][pb[p]] + half * 2);
            }
        }
    }

    const int grp = lane >> 2, tig = lane & 3;
    #pragma unroll
    for (int mt = 0; mt < 2; mt++) {
        #pragma unroll
        for (int nt = 0; nt < 8; nt++) {
            int col = n0 + wn * 64 + nt * 8 + tig * 2;
            float b0 = bias[col], b1 = bias[col + 1];
            #pragma unroll
            for (int hrow = 0; hrow < 2; hrow++) {
                int row = m0 + wm * 32 + mt * 16 + grp + hrow * 8;
                if (row >= M) continue;
                float vx = c[mt][nt][hrow * 2 + 0] + b0;
                float vy = c[mt][nt][hrow * 2 + 1] + b1;
                if (act == 1) {
                    vx = fmaxf(vx, 0.f); vy = fmaxf(vy, 0.f);
                } else if (act == 2) {
                    vx = 0.5f * vx * (1.f + erff(vx * 0.7071067811865475f));
                    vy = 0.5f * vy * (1.f + erff(vy * 0.7071067811865475f));
                }
                size_t off = (size_t)row * N + col;
                if (res) {
                    float2 r = *(const float2*)(res + off);
                    vx += r.x; vy += r.y;
                }
                if (o0) {
                    split_store(o0, o1, off, vx, vy);
                } else {
                    float2 o; o.x = vx; o.y = vy;
                    *(float2*)(C + off) = o;
                }
            }
        }
    }
}

// ---- chunk mean (parallel over 4 dim groups) ----
__global__ void chunk_avg_kernel(const float* __restrict__ h, const int* __restrict__ ids,
                                 float* __restrict__ avg) {
    int c = blockIdx.x, b = blockIdx.y, dg = blockIdx.z;
    __shared__ float msk[CS_];
    __shared__ float s_cnt;
    int tid = threadIdx.x;
    if (tid < CS_) msk[tid] = (ids[b * S_ + c * CS_ + tid] != 0) ? 1.f : 0.f;
    __syncthreads();
    if (tid == 0) {
        float cn = 0.f;
        for (int p = 0; p < CS_; p++) cn += msk[p];
        s_cnt = cn;
    }
    __syncthreads();
    float inv = 1.f / (s_cnt + 1e-10f);
    int d = dg * 256 + tid;
    float s = 0.f;
    for (int p = 0; p < CS_; p++)
        s += h[(size_t)(b * S_ + c * CS_ + p) * H_ + d] * msk[p];
    avg[(size_t)(b * NC_ + c) * H_ + d] = s * inv;
}

// ---- topk ----
__global__ void __launch_bounds__(512)
topk_kernel(const float* __restrict__ qe, const float* __restrict__ cenc,
            unsigned* __restrict__ sel) {
    int s = blockIdx.x, b = blockIdx.y;
    int tid = threadIdx.x, warp = tid >> 5, lane = tid & 31;
    __shared__ float sc[NC_];
    const float* q = qe + (size_t)(b * S_ + s) * H_;
    const float* c = cenc + (size_t)(b * NC_ + warp) * H_;
    float d = 0.f;
    for (int e = lane; e < H_; e += 32) d += q[e] * c[e];
    d = warpSum(d);
    if (lane == 0) sc[warp] = d;
    __syncthreads();
    if (tid == 0) {
        unsigned chosen = 0;
        for (int t = 0; t < TOPK_; t++) {
            float best = -INFINITY;
            int bi = 0;
            for (int cc = 0; cc < NC_; cc++)
                if (!((chosen >> cc) & 1u) && sc[cc] > best) { best = sc[cc]; bi = cc; }
            chosen |= 1u << bi;
        }
        sel[b * S_ + s] = chosen;
    }
}

// ---- LayerNorm (fused split output) ----
__global__ void ln_kernel(const float* __restrict__ x, const float* __restrict__ g,
                          const float* __restrict__ bt,
                          __nv_bfloat16* __restrict__ o0, __nv_bfloat16* __restrict__ o1) {
    int r = blockIdx.x;
    int tid = threadIdx.x, warp = tid >> 5, lane = tid & 31;
    const float* xr = x + (size_t)r * H_;
    float s = 0.f, sq = 0.f;
    for (int e = tid; e < H_; e += 256) {
        float v = xr[e];
        s += v; sq += v * v;
    }
    __shared__ float rs[8], rq[8];
    __shared__ float s_mean, s_rstd;
    s = warpSum(s); sq = warpSum(sq);
    if (lane == 0) { rs[warp] = s; rq[warp] = sq; }
    __syncthreads();
    if (tid == 0) {
        float Sm = 0.f, Q = 0.f;
        for (int ww = 0; ww < 8; ww++) { Sm += rs[ww]; Q += rq[ww]; }
        float mean = Sm / (float)H_;
        float var = Q / (float)H_ - mean * mean;
        s_mean = mean;
        s_rstd = rsqrtf(var + 1e-5f);
    }
    __syncthreads();
    float mean = s_mean, rstd = s_rstd;
    size_t base = (size_t)r * H_;
    for (int e = tid * 2; e < H_; e += 512) {
        float vx = (xr[e] - mean) * rstd * g[e] + bt[e];
        float vy = (xr[e + 1] - mean) * rstd * g[e + 1] + bt[e + 1];
        split_store(o0, o1, base + e, vx, vy);
    }
}

// ---- HMMA sparse chunk attention: 32 queries/block, K/V loads split-waited ----
// FULL=1: 4 products (fp32-equiv). FULL=0: 3 products (layer feeding only logits).
#define AST 136
#define KOFF0 0
#define KOFF1 34816
#define VOFF0 69632
#define VOFF1 104448
#define QOFF0 139264
#define QOFF1 147968
#define NOFF  156672
#define DOFF  173056
#define ASMEM 173184

template<int FULL>
__global__ void __launch_bounds__(256)
attn_kernel(const __nv_bfloat16* __restrict__ qkv0, const __nv_bfloat16* __restrict__ qkv1,
            const unsigned* __restrict__ sel,
            __nv_bfloat16* __restrict__ out0, __nv_bfloat16* __restrict__ out1) {
    extern __shared__ char sm[];
    const uint32_t sb = smem_u32(sm);
    const int tid = threadIdx.x, lane = tid & 31;
    const int w = tid >> 5, gq = w >> 2, wq = w & 3;
    const int g_tid = tid & 127;
    const int head = blockIdx.y, b = blockIdx.z;
    const int s0 = blockIdx.x * 32;
    float* num = (float*)(sm + NOFF);
    float* den = (float*)(sm + DOFF);
    __shared__ unsigned smask[32];
    __shared__ unsigned s_union;

    for (int i = tid; i < 32 * 128; i += 256) num[i] = 0.f;
    if (tid < 32) { smask[tid] = sel[b * S_ + s0 + tid]; den[tid] = 0.f; }
    __syncthreads();
    if (tid == 0) {
        unsigned u = 0;
        for (int i = 0; i < 32; i++) u |= smask[i];
        s_union = u;
    }
    {
        int row = tid >> 3, sp = tid & 7;
        size_t src = ((size_t)(b * S_ + s0 + row)) * HS_ + head * HD_ + sp * 16;
        int gg = row >> 4, lrow = row & 15;
        uint32_t d = gg * 4352 + lrow * (AST * 2) + sp * 32;
        CPA(sb + QOFF0 + d,      qkv0 + src);
        CPA(sb + QOFF0 + d + 16, qkv0 + src + 8);
        CPA(sb + QOFF1 + d,      qkv1 + src);
        CPA(sb + QOFF1 + d + 16, qkv1 + src + 8);
    }
    CPA_COMMIT();
    CPA_WAIT0();
    __syncthreads();

    uint32_t qf[2][8][4];
    const uint32_t qa = gq * 4352 + (lane & 15) * (AST * 2) + ((lane >> 4) << 4);
    #pragma unroll
    for (int s = 0; s < 2; s++)
        #pragma unroll
        for (int ks = 0; ks < 8; ks++) {
            uint32_t ad = sb + (s ? QOFF1 : QOFF0) + qa + ks * 32;
            LDSM_X4(qf[s][ks][0], qf[s][ks][1], qf[s][ks][2], qf[s][ks][3], ad);
        }

    float oacc[16][4];
    #pragma unroll
    for (int t = 0; t < 16; t++)
        #pragma unroll
        for (int e = 0; e < 4; e++) oacc[t][e] = 0.f;

    const unsigned um = s_union;
    const int r0 = lane >> 2, r1 = r0 + 8;
    const uint32_t kb_off = (wq * 32 + (lane & 7) + ((lane >> 4) << 3)) * (AST * 2) + (((lane >> 3) & 1) << 4);
    const uint32_t vb_off = (wq * 32 + (lane & 15)) * (AST * 2) + ((lane >> 4) << 4);

    for (int c = 0; c < NC_; c++) {
        if (!((um >> c) & 1u)) continue;
        int j0 = c * CS_;
        // K then V as separate commit groups; QK overlaps V's in-flight copy
        {
            int row = tid >> 1, hf = tid & 1;
            size_t src = ((size_t)(b * S_ + j0 + row)) * HS_ + head * HD_ + hf * 64;
            uint32_t d = row * (AST * 2) + hf * 128;
            const __nv_bfloat16* k0p = qkv0 + 1024;
            const __nv_bfloat16* k1p = qkv1 + 1024;
            #pragma unroll
            for (int g = 0; g < 8; g++) {
                CPA(sb + KOFF0 + d + g * 16, k0p + src + g * 8);
                CPA(sb + KOFF1 + d + g * 16, k1p + src + g * 8);
            }
            CPA_COMMIT();
            const __nv_bfloat16* v0p = qkv0 + 2048;
            const __nv_bfloat16* v1p = qkv1 + 2048;
            #pragma unroll
            for (int g = 0; g < 8; g++) {
                CPA(sb + VOFF0 + d + g * 16, v0p + src + g * 8);
                CPA(sb + VOFF1 + d + g * 16, v1p + src + g * 8);
            }
            CPA_COMMIT();
        }
        CPA_WAIT1();            // K arrived; V still streaming
        __syncthreads();

        float sc[4][4];
        #pragma unroll
        for (int t = 0; t < 4; t++)
            #pragma unroll
            for (int e = 0; e < 4; e++) sc[t][e] = 0.f;
        #pragma unroll
        for (int ks = 0; ks < 8; ks++) {
            uint32_t kfA0[4], kfA1[4], kfB0[4], kfB1[4];
            LDSM_X4(kfA0[0], kfA0[1], kfA0[2], kfA0[3], sb + KOFF0 + kb_off + ks * 32);
            LDSM_X4(kfB0[0], kfB0[1], kfB0[2], kfB0[3], sb + KOFF0 + kb_off + 16 * AST * 2 + ks * 32);
            LDSM_X4(kfA1[0], kfA1[1], kfA1[2], kfA1[3], sb + KOFF1 + kb_off + ks * 32);
            LDSM_X4(kfB1[0], kfB1[1], kfB1[2], kfB1[3], sb + KOFF1 + kb_off + 16 * AST * 2 + ks * 32);
            #pragma unroll
            for (int qs = 0; qs < 2; qs++) {
                uint32_t* a = qf[qs][ks];
                MMA_BF16(sc[0], a, kfA0 + 0); MMA_BF16(sc[1], a, kfA0 + 2);
                MMA_BF16(sc[2], a, kfB0 + 0); MMA_BF16(sc[3], a, kfB0 + 2);
                if (FULL || qs == 0) {
                    MMA_BF16(sc[0], a, kfA1 + 0); MMA_BF16(sc[1], a, kfA1 + 2);
                    MMA_BF16(sc[2], a, kfB1 + 0); MMA_BF16(sc[3], a, kfB1 + 2);
                }
            }
        }
        bool m0 = (smask[gq * 16 + r0] >> c) & 1u, m1 = (smask[gq * 16 + r1] >> c) & 1u;
        float d0 = 0.f, d1 = 0.f;
        uint32_t pf[2][2][4];
        #pragma unroll
        for (int t = 0; t < 4; t++) {
            float e0 = m0 ? expf(sc[t][0] * SCALE_) : 0.f;
            float e1 = m0 ? expf(sc[t][1] * SCALE_) : 0.f;
            float e2 = m1 ? expf(sc[t][2] * SCALE_) : 0.f;
            float e3 = m1 ? expf(sc[t][3] * SCALE_) : 0.f;
            d0 += e0 + e1; d1 += e2 + e3;
            float h0 = __bfloat162float(__float2bfloat16_rn(e0));
            float h1 = __bfloat162float(__float2bfloat16_rn(e1));
            float h2 = __bfloat162float(__float2bfloat16_rn(e2));
            float h3 = __bfloat162float(__float2bfloat16_rn(e3));
            int g = t >> 1, o = (t & 1) * 2;
            pf[g][0][o + 0] = packbf(h0, h1);
            pf[g][0][o + 1] = packbf(h2, h3);
            pf[g][1][o + 0] = packbf(e0 - h0, e1 - h1);
            pf[g][1][o + 1] = packbf(e2 - h2, e3 - h3);
        }
        d0 += __shfl_xor_sync(0xffffffffu, d0, 1);
        d0 += __shfl_xor_sync(0xffffffffu, d0, 2);
        d1 += __shfl_xor_sync(0xffffffffu, d1, 1);
        d1 += __shfl_xor_sync(0xffffffffu, d1, 2);
        if ((lane & 3) == 0) {
            atomicAdd(&den[gq * 16 + r0], d0);
            atomicAdd(&den[gq * 16 + r1], d1);
        }
        CPA_WAIT0();            // V arrived
        __syncthreads();
        #pragma unroll
        for (int dg = 0; dg < 8; dg++) {
            #pragma unroll
            for (int kg = 0; kg < 2; kg++) {
                uint32_t vf0[4], vf1[4];
                LDSM_X4T(vf0[0], vf0[1], vf0[2], vf0[3], sb + VOFF0 + vb_off + kg * 16 * AST * 2 + dg * 32);
                LDSM_X4T(vf1[0], vf1[1], vf1[2], vf1[3], sb + VOFF1 + vb_off + kg * 16 * AST * 2 + dg * 32);
                #pragma unroll
                for (int ps = 0; ps < 2; ps++) {
                    uint32_t* a = pf[kg][ps];
                    MMA_BF16(oacc[2 * dg + 0], a, vf0 + 0);
                    MMA_BF16(oacc[2 * dg + 1], a, vf0 + 2);
                    if (FULL || ps == 0) {
                        MMA_BF16(oacc[2 * dg + 0], a, vf1 + 0);
                        MMA_BF16(oacc[2 * dg + 1], a, vf1 + 2);
                    }
                }
            }
        }
        __syncthreads();
    }

    for (int ww = 0; ww < 4; ww++) {
        if (wq == ww) {
            #pragma unroll
            for (int t = 0; t < 16; t++) {
                int dbase = 8 * t + 2 * (lane & 3);
                int rb = gq * 16;
                num[(rb + r0) * 128 + dbase + 0] += oacc[t][0];
                num[(rb + r0) * 128 + dbase + 1] += oacc[t][1];
                num[(rb + r1) * 128 + dbase + 0] += oacc[t][2];
                num[(rb + r1) * 128 + dbase + 1] += oacc[t][3];
            }
        }
        __syncthreads();
    }
    for (int r = 0; r < 16; r += 2) {
        int rr = r + (g_tid >> 6);
        int e = (g_tid & 63) * 2;
        int qrow = gq * 16 + rr;
        float dv = den[qrow];
        float vx = num[qrow * 128 + e] / dv;
        float vy = num[qrow * 128 + e + 1] / dv;
        split_store(out0, out1, ((size_t)(b * S_ + s0 + qrow)) * H_ + head * HD_ + e, vx, vy);
    }
}

// ---- host ----
static __nv_bfloat16 *s_A0, *s_A1, *s_B0, *s_B1, *s_W0, *s_W1, *s_at0, *s_at1;
static float* s_qkvb;

static inline void cvt2(const float* A, __nv_bfloat16* d0, __nv_bfloat16* d1, int n) {
    cvt_split2_kernel<<<(n / 4 + 255) / 256, 256>>>(A, d0, d1, n);
}
static inline void gemm_go(const __nv_bfloat16* A0, const __nv_bfloat16* A1,
                           const float* bias, const float* res,
                           float* C, __nv_bfloat16* o0, __nv_bfloat16* o1,
                           int M, int K, int N, int act, int hi) {
    dim3 grid(N / 256, (M + 127) / 128);
    if (hi)
        gemm_tc_kernel<4><<<grid, 512, GSMEM>>>(A0, A1, s_W0, s_W1, bias, res, C, o0, o1, M, K, N, act);
    else
        gemm_tc_kernel<3><<<grid, 512, GSMEM>>>(A0, A1, s_W0, s_W1, bias, res, C, o0, o1, M, K, N, act);
}
static inline void run_gemm(const __nv_bfloat16* A0, const __nv_bfloat16* A1,
                            const float* W, const float* bias, const float* res,
                            float* C, __nv_bfloat16* o0, __nv_bfloat16* o1,
                            int M, int K, int N, int act, int hi) {
    cvt_t2_kernel<<<dim3(N / 32, K / 32), dim3(32, 8)>>>(W, s_W0, s_W1, K, N);
    gemm_go(A0, A1, bias, res, C, o0, o1, M, K, N, act, hi);
}

extern "C" void kernel_launch(void* const* d_in, const int* in_sizes, int n_in,
                              void* d_out, int out_size) {
    const int*   ids     = (const int*)  d_in[0];
    const float* tok_emb = (const float*)d_in[1];
    const float* pos_emb = (const float*)d_in[2];
    const float* in_w    = (const float*)d_in[3];
    const float* in_b    = (const float*)d_in[4];
    const float* ch_w1   = (const float*)d_in[5];
    const float* ch_b1   = (const float*)d_in[6];
    const float* ch_w2   = (const float*)d_in[7];
    const float* ch_b2   = (const float*)d_in[8];
    const float* qe_w1   = (const float*)d_in[9];
    const float* qe_b1   = (const float*)d_in[10];
    const float* qe_w2   = (const float*)d_in[11];
    const float* qe_b2   = (const float*)d_in[12];
    const float* q_w     = (const float*)d_in[13];
    const float* q_b     = (const float*)d_in[14];
    const float* k_w     = (const float*)d_in[15];
    const float* k_b     = (const float*)d_in[16];
    const float* v_w     = (const float*)d_in[17];
    const float* v_b     = (const float*)d_in[18];
    const float* o_w     = (const float*)d_in[19];
    const float* o_b     = (const float*)d_in[20];
    const float* f_w1    = (const float*)d_in[21];
    const float* f_b1    = (const float*)d_in[22];
    const float* f_w2    = (const float*)d_in[23];
    const float* f_b2    = (const float*)d_in[24];
    const float* ln1_g   = (const float*)d_in[25];
    const float* ln1_b   = (const float*)d_in[26];
    const float* ln2_g   = (const float*)d_in[27];
    const float* ln2_b   = (const float*)d_in[28];
    const float* out_w   = (const float*)d_in[29];
    const float* out_b   = (const float*)d_in[30];
    float* logits = (float*)d_out;

    cudaFuncSetAttribute(gemm_tc_kernel<4>, cudaFuncAttributeMaxDynamicSharedMemorySize, GSMEM);
    cudaFuncSetAttribute(gemm_tc_kernel<3>, cudaFuncAttributeMaxDynamicSharedMemorySize, GSMEM);
    cudaFuncSetAttribute(attn_kernel<1>, cudaFuncAttributeMaxDynamicSharedMemorySize, ASMEM);
    cudaFuncSetAttribute(attn_kernel<0>, cudaFuncAttributeMaxDynamicSharedMemorySize, ASMEM);

    float *h, *x, *avg, *cenc;
    unsigned* sel;
    cudaGetSymbolAddress((void**)&h,    g_h);
    cudaGetSymbolAddress((void**)&x,    g_x);
    cudaGetSymbolAddress((void**)&avg,  g_avg);
    cudaGetSymbolAddress((void**)&cenc, g_cenc);
    cudaGetSymbolAddress((void**)&sel,  g_sel);
    cudaGetSymbolAddress((void**)&s_A0, g_A0);
    cudaGetSymbolAddress((void**)&s_A1, g_A1);
    cudaGetSymbolAddress((void**)&s_B0, g_B0);
    cudaGetSymbolAddress((void**)&s_B1, g_B1);
    cudaGetSymbolAddress((void**)&s_W0, g_W0);
    cudaGetSymbolAddress((void**)&s_W1, g_W1);
    cudaGetSymbolAddress((void**)&s_at0, g_at0);
    cudaGetSymbolAddress((void**)&s_at1, g_at1);
    cudaGetSymbolAddress((void**)&s_qkvb, g_qkvb);

    // embeddings (split) -> in-proj -> h (fp32)
    embed_kernel<<<R_, 256>>>(ids, tok_emb, pos_emb, s_A0, s_A1);
    run_gemm(s_A0, s_A1, in_w, in_b, nullptr, h, nullptr, nullptr, R_, E_, H_, 0, 1);

    // chunk encodings
    chunk_avg_kernel<<<dim3(NC_, B_, 4), 256>>>(h, ids, avg);
    cvt2(avg, s_A0, s_A1, B_ * NC_ * H_);
    run_gemm(s_A0, s_A1, ch_w1, ch_b1, nullptr, nullptr, s_B0, s_B1, B_ * NC_, H_, HH_, 1, 1);
    run_gemm(s_B0, s_B1, ch_w2, ch_b2, nullptr, cenc, nullptr, nullptr, B_ * NC_, HH_, H_, 0, 1);

    for (int i = 0; i < L_; i++) {
        // selection path (hi precision)
        cvt2(h, s_A0, s_A1, R_ * H_);
        run_gemm(s_A0, s_A1, qe_w1, qe_b1, nullptr, nullptr, s_B0, s_B1, R_, H_, HH_, 1, 1);
        run_gemm(s_B0, s_B1, qe_w2, qe_b2, nullptr, x, nullptr, nullptr, R_, HH_, H_, 0, 1);
        topk_kernel<<<dim3(S_, B_), 512>>>(x, cenc, sel);

        int hi = (i == 0) ? 1 : 0;
        ln_kernel<<<R_, 256>>>(h, ln1_g + i * H_, ln1_b + i * H_, s_A0, s_A1);
        // merged qkv
        cvt_t2_kernel<<<dim3(32, 32), dim3(32, 8)>>>(q_w + (size_t)i * H_ * H_, s_W0, s_W1, H_, H_);
        cvt_t2_kernel<<<dim3(32, 32), dim3(32, 8)>>>(k_w + (size_t)i * H_ * H_,
            s_W0 + (size_t)H_ * H_, s_W1 + (size_t)H_ * H_, H_, H_);
        cvt_t2_kernel<<<dim3(32, 32), dim3(32, 8)>>>(v_w + (size_t)i * H_ * H_,
            s_W0 + (size_t)2 * H_ * H_, s_W1 + (size_t)2 * H_ * H_, H_, H_);
        cudaMemcpyAsync(s_qkvb,        q_b + i * H_, H_ * 4, cudaMemcpyDeviceToDevice);
        cudaMemcpyAsync(s_qkvb + H_,   k_b + i * H_, H_ * 4, cudaMemcpyDeviceToDevice);
        cudaMemcpyAsync(s_qkvb + 2*H_, v_b + i * H_, H_ * 4, cudaMemcpyDeviceToDevice);
        gemm_go(s_A0, s_A1, s_qkvb, nullptr, nullptr, s_at0, s_at1, R_, H_, HS_, 0, hi);

        if (i == 0)
            attn_kernel<1><<<dim3(S_ / 32, NH_, B_), 256, ASMEM>>>(s_at0, s_at1, sel, s_B0, s_B1);
        else
            attn_kernel<0><<<dim3(S_ / 32, NH_, B_), 256, ASMEM>>>(s_at0, s_at1, sel, s_B0, s_B1);
        run_gemm(s_B0, s_B1, o_w + (size_t)i * H_ * H_, o_b + i * H_, h, h, nullptr, nullptr,
                 R_, H_, H_, 0, hi);

        ln_kernel<<<R_, 256>>>(h, ln2_g + i * H_, ln2_b + i * H_, s_A0, s_A1);
        run_gemm(s_A0, s_A1, f_w1 + (size_t)i * H_ * FF_, f_b1 + i * FF_, nullptr, nullptr,
                 s_B0, s_B1, R_, H_, FF_, 2, hi);
        if (i == L_ - 1) {
            // final ffn2: fused residual + split output, skip fp32 round-trip
            run_gemm(s_B0, s_B1, f_w2 + (size_t)i * FF_ * H_, f_b2 + i * H_, h, nullptr,
                     s_A0, s_A1, R_, FF_, H_, 0, hi);
        } else {
            run_gemm(s_B0, s_B1, f_w2 + (size_t)i * FF_ * H_, f_b2 + i * H_, h, h, nullptr, nullptr,
                     R_, FF_, H_, 0, hi);
        }
    }

    run_gemm(s_A0, s_A1, out_w, out_b, nullptr, logits, nullptr, nullptr, R_, H_, V_, 0, 0);
}

// round 16
// speedup vs baseline: 1.0154x; 1.0094x over previous
#include <cuda_runtime.h>
#include <cuda_bf16.h>
#include <math.h>
#include <stdint.h>

#define B_  2
#define S_  2048
#define E_  1024
#define H_  1024
#define NH_ 8
#define HD_ 128
#define L_  2
#define V_  32000
#define CS_ 128
#define NC_ 16
#define TOPK_ 8
#define R_  (B_ * S_)
#define FF_ (4 * H_)
#define HH_ (H_ / 2)
#define HS_ 3072
#define SCALE_ 0.08838834764831843f

// ---- scratch ----
__device__ __align__(16) float g_h  [R_ * H_];
__device__ __align__(16) float g_x  [R_ * H_];
__device__ __align__(16) float g_avg [B_ * NC_ * H_];
__device__ __align__(16) float g_cenc[B_ * NC_ * H_];
__device__ __align__(16) float g_qkvb[HS_];
__device__ unsigned g_sel[R_];
__device__ __align__(16) __nv_bfloat16 g_A0[R_ * FF_];
__device__ __align__(16) __nv_bfloat16 g_A1[R_ * FF_];
__device__ __align__(16) __nv_bfloat16 g_B0[R_ * FF_];
__device__ __align__(16) __nv_bfloat16 g_B1[R_ * FF_];
__device__ __align__(16) __nv_bfloat16 g_W0[32000 * 1024];
__device__ __align__(16) __nv_bfloat16 g_W1[32000 * 1024];
__device__ __align__(16) __nv_bfloat16 g_at0[R_ * HS_];
__device__ __align__(16) __nv_bfloat16 g_at1[R_ * HS_];

// ---- helpers ----
__device__ __forceinline__ float warpSum(float v) {
    #pragma unroll
    for (int o = 16; o > 0; o >>= 1) v += __shfl_xor_sync(0xffffffffu, v, o);
    return v;
}
__device__ __forceinline__ uint32_t smem_u32(const void* p) {
    uint32_t a;
    asm("{ .reg .u64 t; cvta.to.shared.u64 t, %1; cvt.u32.u64 %0, t; }" : "=r"(a) : "l"(p));
    return a;
}
#define CPA(d, s) asm volatile("cp.async.cg.shared.global [%0], [%1], 16;" :: "r"(d), "l"(s))
#define CPA_COMMIT() asm volatile("cp.async.commit_group;" ::: "memory")
#define CPA_WAIT0()  asm volatile("cp.async.wait_group 0;" ::: "memory")

#define LDSM_X4(r0, r1, r2, r3, a) \
    asm volatile("ldmatrix.sync.aligned.m8n8.x4.shared.b16 {%0,%1,%2,%3}, [%4];" \
        : "=r"(r0), "=r"(r1), "=r"(r2), "=r"(r3) : "r"(a))
#define LDSM_X4T(r0, r1, r2, r3, a) \
    asm volatile("ldmatrix.sync.aligned.m8n8.x4.trans.shared.b16 {%0,%1,%2,%3}, [%4];" \
        : "=r"(r0), "=r"(r1), "=r"(r2), "=r"(r3) : "r"(a))

#define MMA_BF16(c, a, b) \
    asm volatile("mma.sync.aligned.m16n8k16.row.col.f32.bf16.bf16.f32 " \
        "{%0,%1,%2,%3}, {%4,%5,%6,%7}, {%8,%9}, {%0,%1,%2,%3};" \
        : "+f"((c)[0]), "+f"((c)[1]), "+f"((c)[2]), "+f"((c)[3]) \
        : "r"((a)[0]), "r"((a)[1]), "r"((a)[2]), "r"((a)[3]), "r"((b)[0]), "r"((b)[1]))

__device__ __forceinline__ uint32_t packbf(float lo, float hi) {
    __nv_bfloat162 t = __floats2bfloat162_rn(lo, hi);
    return *(uint32_t*)&t;
}
__device__ __forceinline__ void split_store(__nv_bfloat16* o0, __nv_bfloat16* o1,
                                            size_t off, float vx, float vy) {
    float hx = __bfloat162float(__float2bfloat16_rn(vx));
    float hy = __bfloat162float(__float2bfloat16_rn(vy));
    *(uint32_t*)(o0 + off) = packbf(hx, hy);
    *(uint32_t*)(o1 + off) = packbf(vx - hx, vy - hy);
}

// ---- embedding (fused split output) ----
__global__ void embed_kernel(const int* __restrict__ ids, const float* __restrict__ tok,
                             const float* __restrict__ pos,
                             __nv_bfloat16* __restrict__ o0, __nv_bfloat16* __restrict__ o1) {
    int r = blockIdx.x;
    int id = ids[r];
    const float* t = tok + (size_t)id * E_;
    const float* p = pos + (size_t)(r % S_) * E_;
    size_t base = (size_t)r * E_;
    for (int e = threadIdx.x * 2; e < E_; e += blockDim.x * 2) {
        float vx = t[e] + p[e];
        float vy = t[e + 1] + p[e + 1];
        split_store(o0, o1, base + e, vx, vy);
    }
}

// ---- fp32 -> 2-way bf16 split ----
__global__ void cvt_split2_kernel(const float* __restrict__ a, __nv_bfloat16* __restrict__ o0,
                                  __nv_bfloat16* __restrict__ o1, int n) {
    int i = (blockIdx.x * blockDim.x + threadIdx.x) * 4;
    if (i >= n) return;
    float4 v = *(const float4*)(a + i);
    union { __nv_bfloat16 b[4]; uint2 u; } U0, U1;
    float f[4] = {v.x, v.y, v.z, v.w};
    #pragma unroll
    for (int j = 0; j < 4; j++) {
        __nv_bfloat16 b0 = __float2bfloat16_rn(f[j]);
        U0.b[j] = b0;
        U1.b[j] = __float2bfloat16_rn(f[j] - __bfloat162float(b0));
    }
    *(uint2*)(o0 + i) = U0.u;
    *(uint2*)(o1 + i) = U1.u;
}

// ---- fp32 W[K,N] -> 2-way split W^T[N,K] ----
__global__ void cvt_t2_kernel(const float* __restrict__ w, __nv_bfloat16* __restrict__ o0,
                              __nv_bfloat16* __restrict__ o1, int Kd, int Nd) {
    __shared__ float t[32][33];
    int n0 = blockIdx.x * 32, k0 = blockIdx.y * 32;
    int tx = threadIdx.x, ty = threadIdx.y;
    #pragma unroll
    for (int i = 0; i < 32; i += 8)
        t[ty + i][tx] = w[(size_t)(k0 + ty + i) * Nd + n0 + tx];
    __syncthreads();
    #pragma unroll
    for (int i = 0; i < 32; i += 8) {
        float v = t[tx][ty + i];
        __nv_bfloat16 b0 = __float2bfloat16_rn(v);
        size_t o = (size_t)(n0 + ty + i) * Kd + k0 + tx;
        o0[o] = b0;
        o1[o] = __float2bfloat16_rn(v - __bfloat162float(b0));
    }
}

// ---- HMMA split-bf16 GEMM (BK=64, 2-stage, 512 threads, warp tile 32x64) ----
#define SK 72
#define A_MAT (128 * SK * 2)
#define B_MAT (256 * SK * 2)
#define STG (2 * A_MAT + 2 * B_MAT)
#define GSMEM (2 * STG)

template<int NP>
__global__ void __launch_bounds__(512)
gemm_tc_kernel(const __nv_bfloat16* __restrict__ A0, const __nv_bfloat16* __restrict__ A1,
               const __nv_bfloat16* __restrict__ B0, const __nv_bfloat16* __restrict__ B1,
               const float* __restrict__ bias, const float* __restrict__ res,
               float* __restrict__ C, __nv_bfloat16* __restrict__ o0,
               __nv_bfloat16* __restrict__ o1, int M, int K, int N, int act) {
    extern __shared__ char smem[];
    const uint32_t sb = smem_u32(smem);
    const int tid = threadIdx.x, lane = tid & 31;
    const int w = tid >> 5, wm = w >> 2, wn = w & 3;
    const int m0 = blockIdx.y * 128, n0 = blockIdx.x * 256;

    float c[2][8][4];
    #pragma unroll
    for (int i = 0; i < 2; i++)
        #pragma unroll
        for (int j = 0; j < 8; j++)
            #pragma unroll
            for (int e = 0; e < 4; e++) c[i][j][e] = 0.f;

    const int arow = tid >> 3, aseg = tid & 7;
    int agrow_t = (m0 + arow < M) ? (m0 + arow) : (M - 1);
    const int arow2 = (tid + 512) >> 3, aseg2 = (tid + 512) & 7;
    int agrow2_t = (m0 + arow2 < M) ? (m0 + arow2) : (M - 1);

    auto issue_stage = [&](int kb, int st) {
        size_t gk = (size_t)kb * 64;
        uint32_t stb = sb + st * STG;
        {
            uint32_t d = stb + (arow * SK + aseg * 8) * 2;
            size_t o = (size_t)agrow_t * K + gk + aseg * 8;
            CPA(d, A0 + o);
            CPA(d + A_MAT, A1 + o);
            uint32_t d2 = stb + (arow2 * SK + aseg2 * 8) * 2;
            size_t o2 = (size_t)agrow2_t * K + gk + aseg2 * 8;
            CPA(d2, A0 + o2);
            CPA(d2 + A_MAT, A1 + o2);
        }
        #pragma unroll
        for (int i = 0; i < 4; i++) {
            int idx = tid + i * 512;
            int r = idx >> 3, sg = idx & 7;
            uint32_t d = stb + 2 * A_MAT + (r * SK + sg * 8) * 2;
            size_t o = (size_t)(n0 + r) * K + gk + sg * 8;
            CPA(d, B0 + o);
            CPA(d + B_MAT, B1 + o);
        }
        CPA_COMMIT();
    };

    const int nkb = K >> 6;
    issue_stage(0, 0);

    const uint32_t a_off = ((wm * 32 + (lane & 15)) * SK + ((lane >> 4) << 3)) * 2;
    const uint32_t b_off = ((wn * 64 + (lane & 7) + ((lane >> 4) << 3)) * SK + (((lane >> 3) & 1) << 3)) * 2;
    const int pa[4] = {0, 0, 1, 1};
    const int pb[4] = {0, 1, 0, 1};

    for (int kb = 0; kb < nkb; kb++) {
        CPA_WAIT0();
        __syncthreads();
        if (kb + 1 < nkb) issue_stage(kb + 1, (kb + 1) & 1);
        uint32_t base = sb + (kb & 1) * STG;
        #pragma unroll
        for (int kk = 0; kk < 4; kk++) {
            uint32_t af[2][2][4];
            #pragma unroll
            for (int s = 0; s < 2; s++)
                #pragma unroll
                for (int mt = 0; mt < 2; mt++) {
                    uint32_t ad = base + s * A_MAT + a_off + kk * 32 + mt * 16 * SK * 2;
                    LDSM_X4(af[s][mt][0], af[s][mt][1], af[s][mt][2], af[s][mt][3], ad);
                }
            uint32_t bf[2][2][4];
            #pragma unroll
            for (int s = 0; s < 2; s++) {
                uint32_t bd = base + 2 * A_MAT + s * B_MAT + b_off + kk * 32;
                LDSM_X4(bf[0][s][0], bf[0][s][1], bf[0][s][2], bf[0][s][3], bd);
            }
            #pragma unroll
            for (int nt2 = 0; nt2 < 4; nt2++) {
                int cur = nt2 & 1, nxt = cur ^ 1;
                if (nt2 < 3) {
                    #pragma unroll
                    for (int s = 0; s < 2; s++) {
                        uint32_t bd = base + 2 * A_MAT + s * B_MAT + b_off + kk * 32 + (nt2 + 1) * 16 * SK * 2;
                        LDSM_X4(bf[nxt][s][0], bf[nxt][s][1], bf[nxt][s][2], bf[nxt][s][3], bd);
                    }
                }
                #pragma unroll
                for (int p = 0; p < NP; p++)
                    #pragma unroll
                    for (int mt = 0; mt < 2; mt++)
                        #pragma unroll
                        for (int half = 0; half < 2; half++)
                            MMA_BF16(c[mt][nt2 * 2 + half], af[pa[p]][mt], bf[cur][pb[p]] + half * 2);
            }
        }
    }

    const int grp = lane >> 2, tig = lane & 3;
    #pragma unroll
    for (int mt = 0; mt < 2; mt++) {
        #pragma unroll
        for (int nt = 0; nt < 8; nt++) {
            int col = n0 + wn * 64 + nt * 8 + tig * 2;
            float b0 = bias[col], b1 = bias[col + 1];
            #pragma unroll
            for (int hrow = 0; hrow < 2; hrow++) {
                int row = m0 + wm * 32 + mt * 16 + grp + hrow * 8;
                if (row >= M) continue;
                float vx = c[mt][nt][hrow * 2 + 0] + b0;
                float vy = c[mt][nt][hrow * 2 + 1] + b1;
                if (act == 1) {
                    vx = fmaxf(vx, 0.f); vy = fmaxf(vy, 0.f);
                } else if (act == 2) {
                    vx = 0.5f * vx * (1.f + erff(vx * 0.7071067811865475f));
                    vy = 0.5f * vy * (1.f + erff(vy * 0.7071067811865475f));
                }
                size_t off = (size_t)row * N + col;
                if (o0) {
                    split_store(o0, o1, off, vx, vy);
                } else {
                    if (res) {
                        float2 r = *(const float2*)(res + off);
                        vx += r.x; vy += r.y;
                    }
                    float2 o; o.x = vx; o.y = vy;
                    *(float2*)(C + off) = o;
                }
            }
        }
    }
}

// ---- chunk mean (parallel over 4 dim groups) ----
__global__ void chunk_avg_kernel(const float* __restrict__ h, const int* __restrict__ ids,
                                 float* __restrict__ avg) {
    int c = blockIdx.x, b = blockIdx.y, dg = blockIdx.z;
    __shared__ float msk[CS_];
    __shared__ float s_cnt;
    int tid = threadIdx.x;
    if (tid < CS_) msk[tid] = (ids[b * S_ + c * CS_ + tid] != 0) ? 1.f : 0.f;
    __syncthreads();
    if (tid == 0) {
        float cn = 0.f;
        for (int p = 0; p < CS_; p++) cn += msk[p];
        s_cnt = cn;
    }
    __syncthreads();
    float inv = 1.f / (s_cnt + 1e-10f);
    int d = dg * 256 + tid;
    float s = 0.f;
    for (int p = 0; p < CS_; p++)
        s += h[(size_t)(b * S_ + c * CS_ + p) * H_ + d] * msk[p];
    avg[(size_t)(b * NC_ + c) * H_ + d] = s * inv;
}

// ---- topk ----
__global__ void __launch_bounds__(512)
topk_kernel(const float* __restrict__ qe, const float* __restrict__ cenc,
            unsigned* __restrict__ sel) {
    int s = blockIdx.x, b = blockIdx.y;
    int tid = threadIdx.x, warp = tid >> 5, lane = tid & 31;
    __shared__ float sc[NC_];
    const float* q = qe + (size_t)(b * S_ + s) * H_;
    const float* c = cenc + (size_t)(b * NC_ + warp) * H_;
    float d = 0.f;
    for (int e = lane; e < H_; e += 32) d += q[e] * c[e];
    d = warpSum(d);
    if (lane == 0) sc[warp] = d;
    __syncthreads();
    if (tid == 0) {
        unsigned chosen = 0;
        for (int t = 0; t < TOPK_; t++) {
            float best = -INFINITY;
            int bi = 0;
            for (int cc = 0; cc < NC_; cc++)
                if (!((chosen >> cc) & 1u) && sc[cc] > best) { best = sc[cc]; bi = cc; }
            chosen |= 1u << bi;
        }
        sel[b * S_ + s] = chosen;
    }
}

// ---- LayerNorm (fused split output) ----
__global__ void ln_kernel(const float* __restrict__ x, const float* __restrict__ g,
                          const float* __restrict__ bt,
                          __nv_bfloat16* __restrict__ o0, __nv_bfloat16* __restrict__ o1) {
    int r = blockIdx.x;
    int tid = threadIdx.x, warp = tid >> 5, lane = tid & 31;
    const float* xr = x + (size_t)r * H_;
    float s = 0.f, sq = 0.f;
    for (int e = tid; e < H_; e += 256) {
        float v = xr[e];
        s += v; sq += v * v;
    }
    __shared__ float rs[8], rq[8];
    __shared__ float s_mean, s_rstd;
    s = warpSum(s); sq = warpSum(sq);
    if (lane == 0) { rs[warp] = s; rq[warp] = sq; }
    __syncthreads();
    if (tid == 0) {
        float Sm = 0.f, Q = 0.f;
        for (int ww = 0; ww < 8; ww++) { Sm += rs[ww]; Q += rq[ww]; }
        float mean = Sm / (float)H_;
        float var = Q / (float)H_ - mean * mean;
        s_mean = mean;
        s_rstd = rsqrtf(var + 1e-5f);
    }
    __syncthreads();
    float mean = s_mean, rstd = s_rstd;
    size_t base = (size_t)r * H_;
    for (int e = tid * 2; e < H_; e += 512) {
        float vx = (xr[e] - mean) * rstd * g[e] + bt[e];
        float vy = (xr[e + 1] - mean) * rstd * g[e + 1] + bt[e + 1];
        split_store(o0, o1, base + e, vx, vy);
    }
}

// ---- HMMA sparse chunk attention: 32 queries/block (2x16 groups share K/V) ----
#define AST 136
#define KOFF0 0
#define KOFF1 34816
#define VOFF0 69632
#define VOFF1 104448
#define QOFF0 139264
#define QOFF1 147968
#define NOFF  156672
#define DOFF  173056
#define ASMEM 173184

__global__ void __launch_bounds__(256)
attn_kernel(const __nv_bfloat16* __restrict__ qkv0, const __nv_bfloat16* __restrict__ qkv1,
            const unsigned* __restrict__ sel,
            __nv_bfloat16* __restrict__ out0, __nv_bfloat16* __restrict__ out1) {
    extern __shared__ char sm[];
    const uint32_t sb = smem_u32(sm);
    const int tid = threadIdx.x, lane = tid & 31;
    const int w = tid >> 5, gq = w >> 2, wq = w & 3;
    const int g_tid = tid & 127;
    const int head = blockIdx.y, b = blockIdx.z;
    const int s0 = blockIdx.x * 32;
    float* num = (float*)(sm + NOFF);
    float* den = (float*)(sm + DOFF);
    __shared__ unsigned smask[32];
    __shared__ unsigned s_union;

    for (int i = tid; i < 32 * 128; i += 256) num[i] = 0.f;
    if (tid < 32) { smask[tid] = sel[b * S_ + s0 + tid]; den[tid] = 0.f; }
    __syncthreads();
    if (tid == 0) {
        unsigned u = 0;
        for (int i = 0; i < 32; i++) u |= smask[i];
        s_union = u;
    }
    {
        int row = tid >> 3, sp = tid & 7;
        size_t src = ((size_t)(b * S_ + s0 + row)) * HS_ + head * HD_ + sp * 16;
        int gg = row >> 4, lrow = row & 15;
        uint32_t d = gg * 4352 + lrow * (AST * 2) + sp * 32;
        CPA(sb + QOFF0 + d,      qkv0 + src);
        CPA(sb + QOFF0 + d + 16, qkv0 + src + 8);
        CPA(sb + QOFF1 + d,      qkv1 + src);
        CPA(sb + QOFF1 + d + 16, qkv1 + src + 8);
    }
    CPA_COMMIT();
    CPA_WAIT0();
    __syncthreads();

    uint32_t qf[2][8][4];
    const uint32_t qa = gq * 4352 + (lane & 15) * (AST * 2) + ((lane >> 4) << 4);
    #pragma unroll
    for (int s = 0; s < 2; s++)
        #pragma unroll
        for (int ks = 0; ks < 8; ks++) {
            uint32_t ad = sb + (s ? QOFF1 : QOFF0) + qa + ks * 32;
            LDSM_X4(qf[s][ks][0], qf[s][ks][1], qf[s][ks][2], qf[s][ks][3], ad);
        }

    float oacc[16][4];
    #pragma unroll
    for (int t = 0; t < 16; t++)
        #pragma unroll
        for (int e = 0; e < 4; e++) oacc[t][e] = 0.f;

    const unsigned um = s_union;
    const int r0 = lane >> 2, r1 = r0 + 8;
    const uint32_t kb_off = (wq * 32 + (lane & 7) + ((lane >> 4) << 3)) * (AST * 2) + (((lane >> 3) & 1) << 4);
    const uint32_t vb_off = (wq * 32 + (lane & 15)) * (AST * 2) + ((lane >> 4) << 4);

    for (int c = 0; c < NC_; c++) {
        if (!((um >> c) & 1u)) continue;
        int j0 = c * CS_;
        {
            int row = tid >> 1, hf = tid & 1;
            size_t src = ((size_t)(b * S_ + j0 + row)) * HS_ + head * HD_ + hf * 64;
            uint32_t d = row * (AST * 2) + hf * 128;
            const __nv_bfloat16* k0p = qkv0 + 1024;
            const __nv_bfloat16* k1p = qkv1 + 1024;
            const __nv_bfloat16* v0p = qkv0 + 2048;
            const __nv_bfloat16* v1p = qkv1 + 2048;
            #pragma unroll
            for (int g = 0; g < 8; g++) {
                CPA(sb + KOFF0 + d + g * 16, k0p + src + g * 8);
                CPA(sb + KOFF1 + d + g * 16, k1p + src + g * 8);
                CPA(sb + VOFF0 + d + g * 16, v0p + src + g * 8);
                CPA(sb + VOFF1 + d + g * 16, v1p + src + g * 8);
            }
        }
        CPA_COMMIT();
        CPA_WAIT0();
        __syncthreads();

        float sc[4][4];
        #pragma unroll
        for (int t = 0; t < 4; t++)
            #pragma unroll
            for (int e = 0; e < 4; e++) sc[t][e] = 0.f;
        #pragma unroll
        for (int ks = 0; ks < 8; ks++) {
            uint32_t kfA0[4], kfA1[4], kfB0[4], kfB1[4];
            LDSM_X4(kfA0[0], kfA0[1], kfA0[2], kfA0[3], sb + KOFF0 + kb_off + ks * 32);
            LDSM_X4(kfB0[0], kfB0[1], kfB0[2], kfB0[3], sb + KOFF0 + kb_off + 16 * AST * 2 + ks * 32);
            LDSM_X4(kfA1[0], kfA1[1], kfA1[2], kfA1[3], sb + KOFF1 + kb_off + ks * 32);
            LDSM_X4(kfB1[0], kfB1[1], kfB1[2], kfB1[3], sb + KOFF1 + kb_off + 16 * AST * 2 + ks * 32);
            #pragma unroll
            for (int qs = 0; qs < 2; qs++) {
                uint32_t* a = qf[qs][ks];
                MMA_BF16(sc[0], a, kfA0 + 0); MMA_BF16(sc[1], a, kfA0 + 2);
                MMA_BF16(sc[2], a, kfB0 + 0); MMA_BF16(sc[3], a, kfB0 + 2);
                MMA_BF16(sc[0], a, kfA1 + 0); MMA_BF16(sc[1], a, kfA1 + 2);
                MMA_BF16(sc[2], a, kfB1 + 0); MMA_BF16(sc[3], a, kfB1 + 2);
            }
        }
        bool m0 = (smask[gq * 16 + r0] >> c) & 1u, m1 = (smask[gq * 16 + r1] >> c) & 1u;
        float d0 = 0.f, d1 = 0.f;
        uint32_t pf[2][2][4];
        #pragma unroll
        for (int t = 0; t < 4; t++) {
            float e0 = m0 ? expf(sc[t][0] * SCALE_) : 0.f;
            float e1 = m0 ? expf(sc[t][1] * SCALE_) : 0.f;
            float e2 = m1 ? expf(sc[t][2] * SCALE_) : 0.f;
            float e3 = m1 ? expf(sc[t][3] * SCALE_) : 0.f;
            d0 += e0 + e1; d1 += e2 + e3;
            float h0 = __bfloat162float(__float2bfloat16_rn(e0));
            float h1 = __bfloat162float(__float2bfloat16_rn(e1));
            float h2 = __bfloat162float(__float2bfloat16_rn(e2));
            float h3 = __bfloat162float(__float2bfloat16_rn(e3));
            int g = t >> 1, o = (t & 1) * 2;
            pf[g][0][o + 0] = packbf(h0, h1);
            pf[g][0][o + 1] = packbf(h2, h3);
            pf[g][1][o + 0] = packbf(e0 - h0, e1 - h1);
            pf[g][1][o + 1] = packbf(e2 - h2, e3 - h3);
        }
        d0 += __shfl_xor_sync(0xffffffffu, d0, 1);
        d0 += __shfl_xor_sync(0xffffffffu, d0, 2);
        d1 += __shfl_xor_sync(0xffffffffu, d1, 1);
        d1 += __shfl_xor_sync(0xffffffffu, d1, 2);
        if ((lane & 3) == 0) {
            atomicAdd(&den[gq * 16 + r0], d0);
            atomicAdd(&den[gq * 16 + r1], d1);
        }
        #pragma unroll
        for (int dg = 0; dg < 8; dg++) {
            #pragma unroll
            for (int kg = 0; kg < 2; kg++) {
                uint32_t vf0[4], vf1[4];
                LDSM_X4T(vf0[0], vf0[1], vf0[2], vf0[3], sb + VOFF0 + vb_off + kg * 16 * AST * 2 + dg * 32);
                LDSM_X4T(vf1[0], vf1[1], vf1[2], vf1[3], sb + VOFF1 + vb_off + kg * 16 * AST * 2 + dg * 32);
                #pragma unroll
                for (int ps = 0; ps < 2; ps++) {
                    uint32_t* a = pf[kg][ps];
                    MMA_BF16(oacc[2 * dg + 0], a, vf0 + 0);
                    MMA_BF16(oacc[2 * dg + 1], a, vf0 + 2);
                    MMA_BF16(oacc[2 * dg + 0], a, vf1 + 0);
                    MMA_BF16(oacc[2 * dg + 1], a, vf1 + 2);
                }
            }
        }
        __syncthreads();
    }

    for (int ww = 0; ww < 4; ww++) {
        if (wq == ww) {
            #pragma unroll
            for (int t = 0; t < 16; t++) {
                int dbase = 8 * t + 2 * (lane & 3);
                int rb = gq * 16;
                num[(rb + r0) * 128 + dbase + 0] += oacc[t][0];
                num[(rb + r0) * 128 + dbase + 1] += oacc[t][1];
                num[(rb + r1) * 128 + dbase + 0] += oacc[t][2];
                num[(rb + r1) * 128 + dbase + 1] += oacc[t][3];
            }
        }
        __syncthreads();
    }
    for (int r = 0; r < 16; r += 2) {
        int rr = r + (g_tid >> 6);
        int e = (g_tid & 63) * 2;
        int qrow = gq * 16 + rr;
        float dv = den[qrow];
        float vx = num[qrow * 128 + e] / dv;
        float vy = num[qrow * 128 + e + 1] / dv;
        split_store(out0, out1, ((size_t)(b * S_ + s0 + qrow)) * H_ + head * HD_ + e, vx, vy);
    }
}

// ---- host ----
static __nv_bfloat16 *s_A0, *s_A1, *s_B0, *s_B1, *s_W0, *s_W1, *s_at0, *s_at1;
static float* s_qkvb;

static inline void cvt2(const float* A, __nv_bfloat16* d0, __nv_bfloat16* d1, int n) {
    cvt_split2_kernel<<<(n / 4 + 255) / 256, 256>>>(A, d0, d1, n);
}
static inline void gemm_go(const __nv_bfloat16* A0, const __nv_bfloat16* A1,
                           const float* bias, const float* res,
                           float* C, __nv_bfloat16* o0, __nv_bfloat16* o1,
                           int M, int K, int N, int act, int hi) {
    dim3 grid(N / 256, (M + 127) / 128);
    if (hi)
        gemm_tc_kernel<4><<<grid, 512, GSMEM>>>(A0, A1, s_W0, s_W1, bias, res, C, o0, o1, M, K, N, act);
    else
        gemm_tc_kernel<3><<<grid, 512, GSMEM>>>(A0, A1, s_W0, s_W1, bias, res, C, o0, o1, M, K, N, act);
}
static inline void run_gemm(const __nv_bfloat16* A0, const __nv_bfloat16* A1,
                            const float* W, const float* bias, const float* res,
                            float* C, __nv_bfloat16* o0, __nv_bfloat16* o1,
                            int M, int K, int N, int act, int hi) {
    cvt_t2_kernel<<<dim3(N / 32, K / 32), dim3(32, 8)>>>(W, s_W0, s_W1, K, N);
    gemm_go(A0, A1, bias, res, C, o0, o1, M, K, N, act, hi);
}

extern "C" void kernel_launch(void* const* d_in, const int* in_sizes, int n_in,
                              void* d_out, int out_size) {
    const int*   ids     = (const int*)  d_in[0];
    const float* tok_emb = (const float*)d_in[1];
    const float* pos_emb = (const float*)d_in[2];
    const float* in_w    = (const float*)d_in[3];
    const float* in_b    = (const float*)d_in[4];
    const float* ch_w1   = (const float*)d_in[5];
    const float* ch_b1   = (const float*)d_in[6];
    const float* ch_w2   = (const float*)d_in[7];
    const float* ch_b2   = (const float*)d_in[8];
    const float* qe_w1   = (const float*)d_in[9];
    const float* qe_b1   = (const float*)d_in[10];
    const float* qe_w2   = (const float*)d_in[11];
    const float* qe_b2   = (const float*)d_in[12];
    const float* q_w     = (const float*)d_in[13];
    const float* q_b     = (const float*)d_in[14];
    const float* k_w     = (const float*)d_in[15];
    const float* k_b     = (const float*)d_in[16];
    const float* v_w     = (const float*)d_in[17];
    const float* v_b     = (const float*)d_in[18];
    const float* o_w     = (const float*)d_in[19];
    const float* o_b     = (const float*)d_in[20];
    const float* f_w1    = (const float*)d_in[21];
    const float* f_b1    = (const float*)d_in[22];
    const float* f_w2    = (const float*)d_in[23];
    const float* f_b2    = (const float*)d_in[24];
    const float* ln1_g   = (const float*)d_in[25];
    const float* ln1_b   = (const float*)d_in[26];
    const float* ln2_g   = (const float*)d_in[27];
    const float* ln2_b   = (const float*)d_in[28];
    const float* out_w   = (const float*)d_in[29];
    const float* out_b   = (const float*)d_in[30];
    float* logits = (float*)d_out;

    cudaFuncSetAttribute(gemm_tc_kernel<4>, cudaFuncAttributeMaxDynamicSharedMemorySize, GSMEM);
    cudaFuncSetAttribute(gemm_tc_kernel<3>, cudaFuncAttributeMaxDynamicSharedMemorySize, GSMEM);
    cudaFuncSetAttribute(attn_kernel, cudaFuncAttributeMaxDynamicSharedMemorySize, ASMEM);

    float *h, *x, *avg, *cenc;
    unsigned* sel;
    cudaGetSymbolAddress((void**)&h,    g_h);
    cudaGetSymbolAddress((void**)&x,    g_x);
    cudaGetSymbolAddress((void**)&avg,  g_avg);
    cudaGetSymbolAddress((void**)&cenc, g_cenc);
    cudaGetSymbolAddress((void**)&sel,  g_sel);
    cudaGetSymbolAddress((void**)&s_A0, g_A0);
    cudaGetSymbolAddress((void**)&s_A1, g_A1);
    cudaGetSymbolAddress((void**)&s_B0, g_B0);
    cudaGetSymbolAddress((void**)&s_B1, g_B1);
    cudaGetSymbolAddress((void**)&s_W0, g_W0);
    cudaGetSymbolAddress((void**)&s_W1, g_W1);
    cudaGetSymbolAddress((void**)&s_at0, g_at0);
    cudaGetSymbolAddress((void**)&s_at1, g_at1);
    cudaGetSymbolAddress((void**)&s_qkvb, g_qkvb);

    // embeddings (split) -> in-proj -> h (fp32)
    embed_kernel<<<R_, 256>>>(ids, tok_emb, pos_emb, s_A0, s_A1);
    run_gemm(s_A0, s_A1, in_w, in_b, nullptr, h, nullptr, nullptr, R_, E_, H_, 0, 1);

    // chunk encodings
    chunk_avg_kernel<<<dim3(NC_, B_, 4), 256>>>(h, ids, avg);
    cvt2(avg, s_A0, s_A1, B_ * NC_ * H_);
    run_gemm(s_A0, s_A1, ch_w1, ch_b1, nullptr, nullptr, s_B0, s_B1, B_ * NC_, H_, HH_, 1, 1);
    run_gemm(s_B0, s_B1, ch_w2, ch_b2, nullptr, cenc, nullptr, nullptr, B_ * NC_, HH_, H_, 0, 1);

    for (int i = 0; i < L_; i++) {
        // selection path (hi precision)
        cvt2(h, s_A0, s_A1, R_ * H_);
        run_gemm(s_A0, s_A1, qe_w1, qe_b1, nullptr, nullptr, s_B0, s_B1, R_, H_, HH_, 1, 1);
        run_gemm(s_B0, s_B1, qe_w2, qe_b2, nullptr, x, nullptr, nullptr, R_, HH_, H_, 0, 1);
        topk_kernel<<<dim3(S_, B_), 512>>>(x, cenc, sel);

        int hi = (i == 0) ? 1 : 0;
        ln_kernel<<<R_, 256>>>(h, ln1_g + i * H_, ln1_b + i * H_, s_A0, s_A1);
        // merged qkv: W^T rows [q | k | v], bias concatenated
        cvt_t2_kernel<<<dim3(32, 32), dim3(32, 8)>>>(q_w + (size_t)i * H_ * H_, s_W0, s_W1, H_, H_);
        cvt_t2_kernel<<<dim3(32, 32), dim3(32, 8)>>>(k_w + (size_t)i * H_ * H_,
            s_W0 + (size_t)H_ * H_, s_W1 + (size_t)H_ * H_, H_, H_);
        cvt_t2_kernel<<<dim3(32, 32), dim3(32, 8)>>>(v_w + (size_t)i * H_ * H_,
            s_W0 + (size_t)2 * H_ * H_, s_W1 + (size_t)2 * H_ * H_, H_, H_);
        cudaMemcpyAsync(s_qkvb,        q_b + i * H_, H_ * 4, cudaMemcpyDeviceToDevice);
        cudaMemcpyAsync(s_qkvb + H_,   k_b + i * H_, H_ * 4, cudaMemcpyDeviceToDevice);
        cudaMemcpyAsync(s_qkvb + 2*H_, v_b + i * H_, H_ * 4, cudaMemcpyDeviceToDevice);
        gemm_go(s_A0, s_A1, s_qkvb, nullptr, nullptr, s_at0, s_at1, R_, H_, HS_, 0, hi);

        attn_kernel<<<dim3(S_ / 32, NH_, B_), 256, ASMEM>>>(s_at0, s_at1, sel, s_B0, s_B1);
        run_gemm(s_B0, s_B1, o_w + (size_t)i * H_ * H_, o_b + i * H_, h, h, nullptr, nullptr,
                 R_, H_, H_, 0, hi);

        ln_kernel<<<R_, 256>>>(h, ln2_g + i * H_, ln2_b + i * H_, s_A0, s_A1);
        run_gemm(s_A0, s_A1, f_w1 + (size_t)i * H_ * FF_, f_b1 + i * FF_, nullptr, nullptr,
                 s_B0, s_B1, R_, H_, FF_, 2, hi);
        run_gemm(s_B0, s_B1, f_w2 + (size_t)i * FF_ * H_, f_b2 + i * H_, h, h, nullptr, nullptr,
                 R_, FF_, H_, 0, hi);
    }

    cvt2(h, s_A0, s_A1, R_ * H_);
    run_gemm(s_A0, s_A1, out_w, out_b, nullptr, logits, nullptr, nullptr, R_, H_, V_, 0, 0);
}

// round 17
// speedup vs baseline: 1.1321x; 1.1149x over previous
#include <cuda_runtime.h>
#include <cuda_bf16.h>
#include <math.h>
#include <stdint.h>

#define B_  2
#define S_  2048
#define E_  1024
#define H_  1024
#define NH_ 8
#define HD_ 128
#define L_  2
#define V_  32000
#define CS_ 128
#define NC_ 16
#define TOPK_ 8
#define R_  (B_ * S_)
#define FF_ (4 * H_)
#define HH_ (H_ / 2)
#define HS_ 3072
#define SCALE_ 0.08838834764831843f

// ---- scratch ----
__device__ __align__(16) float g_h  [R_ * H_];
__device__ __align__(16) float g_x  [R_ * H_];
__device__ __align__(16) float g_avg [B_ * NC_ * H_];
__device__ __align__(16) float g_cenc[B_ * NC_ * H_];
__device__ __align__(16) float g_qkvb[HS_];
__device__ unsigned g_sel[R_];
__device__ __align__(16) __nv_bfloat16 g_A0[R_ * FF_];
__device__ __align__(16) __nv_bfloat16 g_A1[R_ * FF_];
__device__ __align__(16) __nv_bfloat16 g_B0[R_ * FF_];
__device__ __align__(16) __nv_bfloat16 g_B1[R_ * FF_];
__device__ __align__(16) __nv_bfloat16 g_W0[32000 * 1024];
__device__ __align__(16) __nv_bfloat16 g_W1[32000 * 1024];
__device__ __align__(16) __nv_bfloat16 g_at0[R_ * HS_];
__device__ __align__(16) __nv_bfloat16 g_at1[R_ * HS_];

// ---- helpers ----
__device__ __forceinline__ float warpSum(float v) {
    #pragma unroll
    for (int o = 16; o > 0; o >>= 1) v += __shfl_xor_sync(0xffffffffu, v, o);
    return v;
}
__device__ __forceinline__ uint32_t smem_u32(const void* p) {
    uint32_t a;
    asm("{ .reg .u64 t; cvta.to.shared.u64 t, %1; cvt.u32.u64 %0, t; }" : "=r"(a) : "l"(p));
    return a;
}
#define CPA(d, s) asm volatile("cp.async.cg.shared.global [%0], [%1], 16;" :: "r"(d), "l"(s))
#define CPA_COMMIT() asm volatile("cp.async.commit_group;" ::: "memory")
#define CPA_WAIT0()  asm volatile("cp.async.wait_group 0;" ::: "memory")
#define CPA_WAIT1()  asm volatile("cp.async.wait_group 1;" ::: "memory")

#define LDSM_X4(r0, r1, r2, r3, a) \
    asm volatile("ldmatrix.sync.aligned.m8n8.x4.shared.b16 {%0,%1,%2,%3}, [%4];" \
        : "=r"(r0), "=r"(r1), "=r"(r2), "=r"(r3) : "r"(a))
#define LDSM_X4T(r0, r1, r2, r3, a) \
    asm volatile("ldmatrix.sync.aligned.m8n8.x4.trans.shared.b16 {%0,%1,%2,%3}, [%4];" \
        : "=r"(r0), "=r"(r1), "=r"(r2), "=r"(r3) : "r"(a))

#define MMA_BF16(c, a, b) \
    asm volatile("mma.sync.aligned.m16n8k16.row.col.f32.bf16.bf16.f32 " \
        "{%0,%1,%2,%3}, {%4,%5,%6,%7}, {%8,%9}, {%0,%1,%2,%3};" \
        : "+f"((c)[0]), "+f"((c)[1]), "+f"((c)[2]), "+f"((c)[3]) \
        : "r"((a)[0]), "r"((a)[1]), "r"((a)[2]), "r"((a)[3]), "r"((b)[0]), "r"((b)[1]))

__device__ __forceinline__ uint32_t packbf(float lo, float hi) {
    __nv_bfloat162 t = __floats2bfloat162_rn(lo, hi);
    return *(uint32_t*)&t;
}
__device__ __forceinline__ void split_store(__nv_bfloat16* o0, __nv_bfloat16* o1,
                                            size_t off, float vx, float vy) {
    float hx = __bfloat162float(__float2bfloat16_rn(vx));
    float hy = __bfloat162float(__float2bfloat16_rn(vy));
    *(uint32_t*)(o0 + off) = packbf(hx, hy);
    *(uint32_t*)(o1 + off) = packbf(vx - hx, vy - hy);
}

// ---- embedding (fused split output) ----
__global__ void embed_kernel(const int* __restrict__ ids, const float* __restrict__ tok,
                             const float* __restrict__ pos,
                             __nv_bfloat16* __restrict__ o0, __nv_bfloat16* __restrict__ o1) {
    int r = blockIdx.x;
    int id = ids[r];
    const float* t = tok + (size_t)id * E_;
    const float* p = pos + (size_t)(r % S_) * E_;
    size_t base = (size_t)r * E_;
    for (int e = threadIdx.x * 2; e < E_; e += blockDim.x * 2) {
        float vx = t[e] + p[e];
        float vy = t[e + 1] + p[e + 1];
        split_store(o0, o1, base + e, vx, vy);
    }
}

// ---- fp32 -> 2-way bf16 split ----
__global__ void cvt_split2_kernel(const float* __restrict__ a, __nv_bfloat16* __restrict__ o0,
                                  __nv_bfloat16* __restrict__ o1, int n) {
    int i = (blockIdx.x * blockDim.x + threadIdx.x) * 4;
    if (i >= n) return;
    float4 v = *(const float4*)(a + i);
    union { __nv_bfloat16 b[4]; uint2 u; } U0, U1;
    float f[4] = {v.x, v.y, v.z, v.w};
    #pragma unroll
    for (int j = 0; j < 4; j++) {
        __nv_bfloat16 b0 = __float2bfloat16_rn(f[j]);
        U0.b[j] = b0;
        U1.b[j] = __float2bfloat16_rn(f[j] - __bfloat162float(b0));
    }
    *(uint2*)(o0 + i) = U0.u;
    *(uint2*)(o1 + i) = U1.u;
}

// ---- fp32 W[K,N] -> 2-way split W^T[N,K] ----
__global__ void cvt_t2_kernel(const float* __restrict__ w, __nv_bfloat16* __restrict__ o0,
                              __nv_bfloat16* __restrict__ o1, int Kd, int Nd) {
    __shared__ float t[32][33];
    int n0 = blockIdx.x * 32, k0 = blockIdx.y * 32;
    int tx = threadIdx.x, ty = threadIdx.y;
    #pragma unroll
    for (int i = 0; i < 32; i += 8)
        t[ty + i][tx] = w[(size_t)(k0 + ty + i) * Nd + n0 + tx];
    __syncthreads();
    #pragma unroll
    for (int i = 0; i < 32; i += 8) {
        float v = t[tx][ty + i];
        __nv_bfloat16 b0 = __float2bfloat16_rn(v);
        size_t o = (size_t)(n0 + ty + i) * Kd + k0 + tx;
        o0[o] = b0;
        o1[o] = __float2bfloat16_rn(v - __bfloat162float(b0));
    }
}

// ---- HMMA split-bf16 GEMM ----
// CTA 128x128, 256 threads (8 warps, 32x64 tiles), BK=32, 3-stage,
// XOR-swizzled smem (64B rows, chunk' = ck ^ ((row>>1)&3)) -> no padding,
// 96KB smem + 128 regs => 2 CTAs/SM (independent barriers hide sync stalls).
#define A_MAT 8192
#define B_MAT 8192
#define STG (2 * A_MAT + 2 * B_MAT)   // 32768
#define GSMEM (3 * STG)               // 98304

__device__ __forceinline__ uint32_t swz(int row, int ck) {
    return (uint32_t)(row * 64 + ((ck ^ ((row >> 1) & 3)) << 4));
}

template<int NP>
__global__ void __launch_bounds__(256, 2)
gemm_tc_kernel(const __nv_bfloat16* __restrict__ A0, const __nv_bfloat16* __restrict__ A1,
               const __nv_bfloat16* __restrict__ B0, const __nv_bfloat16* __restrict__ B1,
               const float* __restrict__ bias, const float* __restrict__ res,
               float* __restrict__ C, __nv_bfloat16* __restrict__ o0,
               __nv_bfloat16* __restrict__ o1, int M, int K, int N, int act) {
    extern __shared__ char smem[];
    const uint32_t sb = smem_u32(smem);
    const int tid = threadIdx.x, lane = tid & 31;
    const int w = tid >> 5, wm = w & 3, wn = w >> 2;   // 4 M-warps x 2 N-warps
    const int m0 = blockIdx.y * 128, n0 = blockIdx.x * 128;

    float c[2][8][4];
    #pragma unroll
    for (int i = 0; i < 2; i++)
        #pragma unroll
        for (int j = 0; j < 8; j++)
            #pragma unroll
            for (int e = 0; e < 4; e++) c[i][j][e] = 0.f;

    int arowi[2], asegi[2], agrowi[2];
    #pragma unroll
    for (int i = 0; i < 2; i++) {
        int cid = tid + i * 256;
        arowi[i] = cid >> 2;
        asegi[i] = cid & 3;
        int gr = m0 + arowi[i];
        agrowi[i] = gr < M ? gr : (M - 1);
    }

    auto issue_stage = [&](int kb, int st) {
        size_t gk = (size_t)kb * 32;
        uint32_t stb = sb + st * STG;
        #pragma unroll
        for (int i = 0; i < 2; i++) {
            uint32_t d = stb + swz(arowi[i], asegi[i]);
            size_t o = (size_t)agrowi[i] * K + gk + asegi[i] * 8;
            CPA(d, A0 + o);
            CPA(d + A_MAT, A1 + o);
        }
        #pragma unroll
        for (int i = 0; i < 2; i++) {
            int cid = tid + i * 256;
            int r = cid >> 2, sg = cid & 3;
            uint32_t d = stb + 2 * A_MAT + swz(r, sg);
            size_t o = (size_t)(n0 + r) * K + gk + sg * 8;
            CPA(d, B0 + o);
            CPA(d + B_MAT, B1 + o);
        }
        CPA_COMMIT();
    };

    const int nkb = K >> 5;
    issue_stage(0, 0);
    if (nkb > 1) issue_stage(1, 1);

    const int a_row_b = wm * 32 + (lane & 15);
    const int a_ck_b  = lane >> 4;
    const int b_row_b = wn * 64 + (lane & 7) + ((lane >> 4) << 3);
    const int b_ck_b  = (lane >> 3) & 1;
    const int pa[4] = {0, 0, 1, 1};
    const int pb[4] = {0, 1, 0, 1};

    for (int kb = 0; kb < nkb; kb++) {
        if (kb + 1 < nkb) CPA_WAIT1(); else CPA_WAIT0();
        __syncthreads();
        uint32_t base = sb + (kb % 3) * STG;
        #pragma unroll
        for (int kk = 0; kk < 2; kk++) {
            uint32_t af[2][2][4];
            #pragma unroll
            for (int s = 0; s < 2; s++)
                #pragma unroll
                for (int mt = 0; mt < 2; mt++) {
                    uint32_t ad = base + s * A_MAT + swz(a_row_b + mt * 16, kk * 2 + a_ck_b);
                    LDSM_X4(af[s][mt][0], af[s][mt][1], af[s][mt][2], af[s][mt][3], ad);
                }
            uint32_t bf[2][2][4];
            #pragma unroll
            for (int s = 0; s < 2; s++) {
                uint32_t bd = base + 2 * A_MAT + s * B_MAT + swz(b_row_b, kk * 2 + b_ck_b);
                LDSM_X4(bf[0][s][0], bf[0][s][1], bf[0][s][2], bf[0][s][3], bd);
            }
            #pragma unroll
            for (int nt2 = 0; nt2 < 4; nt2++) {
                int cur = nt2 & 1, nxt = cur ^ 1;
                if (nt2 < 3) {
                    #pragma unroll
                    for (int s = 0; s < 2; s++) {
                        uint32_t bd = base + 2 * A_MAT + s * B_MAT + swz(b_row_b + (nt2 + 1) * 16, kk * 2 + b_ck_b);
                        LDSM_X4(bf[nxt][s][0], bf[nxt][s][1], bf[nxt][s][2], bf[nxt][s][3], bd);
                    }
                }
                #pragma unroll
                for (int p = 0; p < NP; p++)
                    #pragma unroll
                    for (int mt = 0; mt < 2; mt++)
                        #pragma unroll
                        for (int half = 0; half < 2; half++)
                            MMA_BF16(c[mt][nt2 * 2 + half], af[pa[p]][mt], bf[cur][pb[p]] + half * 2);
            }
        }
        if (kb + 2 < nkb) issue_stage(kb + 2, (kb + 2) % 3);
    }

    const int grp = lane >> 2, tig = lane & 3;
    #pragma unroll
    for (int mt = 0; mt < 2; mt++) {
        #pragma unroll
        for (int nt = 0; nt < 8; nt++) {
            int col = n0 + wn * 64 + nt * 8 + tig * 2;
            float b0 = bias[col], b1 = bias[col + 1];
            #pragma unroll
            for (int hrow = 0; hrow < 2; hrow++) {
                int row = m0 + wm * 32 + mt * 16 + grp + hrow * 8;
                if (row >= M) continue;
                float vx = c[mt][nt][hrow * 2 + 0] + b0;
                float vy = c[mt][nt][hrow * 2 + 1] + b1;
                if (act == 1) {
                    vx = fmaxf(vx, 0.f); vy = fmaxf(vy, 0.f);
                } else if (act == 2) {
                    vx = 0.5f * vx * (1.f + erff(vx * 0.7071067811865475f));
                    vy = 0.5f * vy * (1.f + erff(vy * 0.7071067811865475f));
                }
                size_t off = (size_t)row * N + col;
                if (o0) {
                    split_store(o0, o1, off, vx, vy);
                } else {
                    if (res) {
                        float2 r = *(const float2*)(res + off);
                        vx += r.x; vy += r.y;
                    }
                    float2 o; o.x = vx; o.y = vy;
                    *(float2*)(C + off) = o;
                }
            }
        }
    }
}

// ---- chunk mean (parallel over 4 dim groups) ----
__global__ void chunk_avg_kernel(const float* __restrict__ h, const int* __restrict__ ids,
                                 float* __restrict__ avg) {
    int c = blockIdx.x, b = blockIdx.y, dg = blockIdx.z;
    __shared__ float msk[CS_];
    __shared__ float s_cnt;
    int tid = threadIdx.x;
    if (tid < CS_) msk[tid] = (ids[b * S_ + c * CS_ + tid] != 0) ? 1.f : 0.f;
    __syncthreads();
    if (tid == 0) {
        float cn = 0.f;
        for (int p = 0; p < CS_; p++) cn += msk[p];
        s_cnt = cn;
    }
    __syncthreads();
    float inv = 1.f / (s_cnt + 1e-10f);
    int d = dg * 256 + tid;
    float s = 0.f;
    for (int p = 0; p < CS_; p++)
        s += h[(size_t)(b * S_ + c * CS_ + p) * H_ + d] * msk[p];
    avg[(size_t)(b * NC_ + c) * H_ + d] = s * inv;
}

// ---- topk ----
__global__ void __launch_bounds__(512)
topk_kernel(const float* __restrict__ qe, const float* __restrict__ cenc,
            unsigned* __restrict__ sel) {
    int s = blockIdx.x, b = blockIdx.y;
    int tid = threadIdx.x, warp = tid >> 5, lane = tid & 31;
    __shared__ float sc[NC_];
    const float* q = qe + (size_t)(b * S_ + s) * H_;
    const float* c = cenc + (size_t)(b * NC_ + warp) * H_;
    float d = 0.f;
    for (int e = lane; e < H_; e += 32) d += q[e] * c[e];
    d = warpSum(d);
    if (lane == 0) sc[warp] = d;
    __syncthreads();
    if (tid == 0) {
        unsigned chosen = 0;
        for (int t = 0; t < TOPK_; t++) {
            float best = -INFINITY;
            int bi = 0;
            for (int cc = 0; cc < NC_; cc++)
                if (!((chosen >> cc) & 1u) && sc[cc] > best) { best = sc[cc]; bi = cc; }
            chosen |= 1u << bi;
        }
        sel[b * S_ + s] = chosen;
    }
}

// ---- LayerNorm (fused split output) ----
__global__ void ln_kernel(const float* __restrict__ x, const float* __restrict__ g,
                          const float* __restrict__ bt,
                          __nv_bfloat16* __restrict__ o0, __nv_bfloat16* __restrict__ o1) {
    int r = blockIdx.x;
    int tid = threadIdx.x, warp = tid >> 5, lane = tid & 31;
    const float* xr = x + (size_t)r * H_;
    float s = 0.f, sq = 0.f;
    for (int e = tid; e < H_; e += 256) {
        float v = xr[e];
        s += v; sq += v * v;
    }
    __shared__ float rs[8], rq[8];
    __shared__ float s_mean, s_rstd;
    s = warpSum(s); sq = warpSum(sq);
    if (lane == 0) { rs[warp] = s; rq[warp] = sq; }
    __syncthreads();
    if (tid == 0) {
        float Sm = 0.f, Q = 0.f;
        for (int ww = 0; ww < 8; ww++) { Sm += rs[ww]; Q += rq[ww]; }
        float mean = Sm / (float)H_;
        float var = Q / (float)H_ - mean * mean;
        s_mean = mean;
        s_rstd = rsqrtf(var + 1e-5f);
    }
    __syncthreads();
    float mean = s_mean, rstd = s_rstd;
    size_t base = (size_t)r * H_;
    for (int e = tid * 2; e < H_; e += 512) {
        float vx = (xr[e] - mean) * rstd * g[e] + bt[e];
        float vy = (xr[e + 1] - mean) * rstd * g[e + 1] + bt[e + 1];
        split_store(o0, o1, base + e, vx, vy);
    }
}

// ---- HMMA sparse chunk attention: 32 queries/block (2x16 groups share K/V) ----
#define AST 136
#define KOFF0 0
#define KOFF1 34816
#define VOFF0 69632
#define VOFF1 104448
#define QOFF0 139264
#define QOFF1 147968
#define NOFF  156672
#define DOFF  173056
#define ASMEM 173184

__global__ void __launch_bounds__(256)
attn_kernel(const __nv_bfloat16* __restrict__ qkv0, const __nv_bfloat16* __restrict__ qkv1,
            const unsigned* __restrict__ sel,
            __nv_bfloat16* __restrict__ out0, __nv_bfloat16* __restrict__ out1) {
    extern __shared__ char sm[];
    const uint32_t sb = smem_u32(sm);
    const int tid = threadIdx.x, lane = tid & 31;
    const int w = tid >> 5, gq = w >> 2, wq = w & 3;
    const int g_tid = tid & 127;
    const int head = blockIdx.y, b = blockIdx.z;
    const int s0 = blockIdx.x * 32;
    float* num = (float*)(sm + NOFF);
    float* den = (float*)(sm + DOFF);
    __shared__ unsigned smask[32];
    __shared__ unsigned s_union;

    for (int i = tid; i < 32 * 128; i += 256) num[i] = 0.f;
    if (tid < 32) { smask[tid] = sel[b * S_ + s0 + tid]; den[tid] = 0.f; }
    __syncthreads();
    if (tid == 0) {
        unsigned u = 0;
        for (int i = 0; i < 32; i++) u |= smask[i];
        s_union = u;
    }
    {
        int row = tid >> 3, sp = tid & 7;
        size_t src = ((size_t)(b * S_ + s0 + row)) * HS_ + head * HD_ + sp * 16;
        int gg = row >> 4, lrow = row & 15;
        uint32_t d = gg * 4352 + lrow * (AST * 2) + sp * 32;
        CPA(sb + QOFF0 + d,      qkv0 + src);
        CPA(sb + QOFF0 + d + 16, qkv0 + src + 8);
        CPA(sb + QOFF1 + d,      qkv1 + src);
        CPA(sb + QOFF1 + d + 16, qkv1 + src + 8);
    }
    CPA_COMMIT();
    CPA_WAIT0();
    __syncthreads();

    uint32_t qf[2][8][4];
    const uint32_t qa = gq * 4352 + (lane & 15) * (AST * 2) + ((lane >> 4) << 4);
    #pragma unroll
    for (int s = 0; s < 2; s++)
        #pragma unroll
        for (int ks = 0; ks < 8; ks++) {
            uint32_t ad = sb + (s ? QOFF1 : QOFF0) + qa + ks * 32;
            LDSM_X4(qf[s][ks][0], qf[s][ks][1], qf[s][ks][2], qf[s][ks][3], ad);
        }

    float oacc[16][4];
    #pragma unroll
    for (int t = 0; t < 16; t++)
        #pragma unroll
        for (int e = 0; e < 4; e++) oacc[t][e] = 0.f;

    const unsigned um = s_union;
    const int r0 = lane >> 2, r1 = r0 + 8;
    const uint32_t kb_off = (wq * 32 + (lane & 7) + ((lane >> 4) << 3)) * (AST * 2) + (((lane >> 3) & 1) << 4);
    const uint32_t vb_off = (wq * 32 + (lane & 15)) * (AST * 2) + ((lane >> 4) << 4);

    for (int c = 0; c < NC_; c++) {
        if (!((um >> c) & 1u)) continue;
        int j0 = c * CS_;
        {
            int row = tid >> 1, hf = tid & 1;
            size_t src = ((size_t)(b * S_ + j0 + row)) * HS_ + head * HD_ + hf * 64;
            uint32_t d = row * (AST * 2) + hf * 128;
            const __nv_bfloat16* k0p = qkv0 + 1024;
            const __nv_bfloat16* k1p = qkv1 + 1024;
            const __nv_bfloat16* v0p = qkv0 + 2048;
            const __nv_bfloat16* v1p = qkv1 + 2048;
            #pragma unroll
            for (int g = 0; g < 8; g++) {
                CPA(sb + KOFF0 + d + g * 16, k0p + src + g * 8);
                CPA(sb + KOFF1 + d + g * 16, k1p + src + g * 8);
                CPA(sb + VOFF0 + d + g * 16, v0p + src + g * 8);
                CPA(sb + VOFF1 + d + g * 16, v1p + src + g * 8);
            }
        }
        CPA_COMMIT();
        CPA_WAIT0();
        __syncthreads();

        float sc[4][4];
        #pragma unroll
        for (int t = 0; t < 4; t++)
            #pragma unroll
            for (int e = 0; e < 4; e++) sc[t][e] = 0.f;
        #pragma unroll
        for (int ks = 0; ks < 8; ks++) {
            uint32_t kfA0[4], kfA1[4], kfB0[4], kfB1[4];
            LDSM_X4(kfA0[0], kfA0[1], kfA0[2], kfA0[3], sb + KOFF0 + kb_off + ks * 32);
            LDSM_X4(kfB0[0], kfB0[1], kfB0[2], kfB0[3], sb + KOFF0 + kb_off + 16 * AST * 2 + ks * 32);
            LDSM_X4(kfA1[0], kfA1[1], kfA1[2], kfA1[3], sb + KOFF1 + kb_off + ks * 32);
            LDSM_X4(kfB1[0], kfB1[1], kfB1[2], kfB1[3], sb + KOFF1 + kb_off + 16 * AST * 2 + ks * 32);
            #pragma unroll
            for (int qs = 0; qs < 2; qs++) {
                uint32_t* a = qf[qs][ks];
                MMA_BF16(sc[0], a, kfA0 + 0); MMA_BF16(sc[1], a, kfA0 + 2);
                MMA_BF16(sc[2], a, kfB0 + 0); MMA_BF16(sc[3], a, kfB0 + 2);
                MMA_BF16(sc[0], a, kfA1 + 0); MMA_BF16(sc[1], a, kfA1 + 2);
                MMA_BF16(sc[2], a, kfB1 + 0); MMA_BF16(sc[3], a, kfB1 + 2);
            }
        }
        bool m0 = (smask[gq * 16 + r0] >> c) & 1u, m1 = (smask[gq * 16 + r1] >> c) & 1u;
        float d0 = 0.f, d1 = 0.f;
        uint32_t pf[2][2][4];
        #pragma unroll
        for (int t = 0; t < 4; t++) {
            float e0 = m0 ? expf(sc[t][0] * SCALE_) : 0.f;
            float e1 = m0 ? expf(sc[t][1] * SCALE_) : 0.f;
            float e2 = m1 ? expf(sc[t][2] * SCALE_) : 0.f;
            float e3 = m1 ? expf(sc[t][3] * SCALE_) : 0.f;
            d0 += e0 + e1; d1 += e2 + e3;
            float h0 = __bfloat162float(__float2bfloat16_rn(e0));
            float h1 = __bfloat162float(__float2bfloat16_rn(e1));
            float h2 = __bfloat162float(__float2bfloat16_rn(e2));
            float h3 = __bfloat162float(__float2bfloat16_rn(e3));
            int g = t >> 1, o = (t & 1) * 2;
            pf[g][0][o + 0] = packbf(h0, h1);
            pf[g][0][o + 1] = packbf(h2, h3);
            pf[g][1][o + 0] = packbf(e0 - h0, e1 - h1);
            pf[g][1][o + 1] = packbf(e2 - h2, e3 - h3);
        }
        d0 += __shfl_xor_sync(0xffffffffu, d0, 1);
        d0 += __shfl_xor_sync(0xffffffffu, d0, 2);
        d1 += __shfl_xor_sync(0xffffffffu, d1, 1);
        d1 += __shfl_xor_sync(0xffffffffu, d1, 2);
        if ((lane & 3) == 0) {
            atomicAdd(&den[gq * 16 + r0], d0);
            atomicAdd(&den[gq * 16 + r1], d1);
        }
        #pragma unroll
        for (int dg = 0; dg < 8; dg++) {
            #pragma unroll
            for (int kg = 0; kg < 2; kg++) {
                uint32_t vf0[4], vf1[4];
                LDSM_X4T(vf0[0], vf0[1], vf0[2], vf0[3], sb + VOFF0 + vb_off + kg * 16 * AST * 2 + dg * 32);
                LDSM_X4T(vf1[0], vf1[1], vf1[2], vf1[3], sb + VOFF1 + vb_off + kg * 16 * AST * 2 + dg * 32);
                #pragma unroll
                for (int ps = 0; ps < 2; ps++) {
                    uint32_t* a = pf[kg][ps];
                    MMA_BF16(oacc[2 * dg + 0], a, vf0 + 0);
                    MMA_BF16(oacc[2 * dg + 1], a, vf0 + 2);
                    MMA_BF16(oacc[2 * dg + 0], a, vf1 + 0);
                    MMA_BF16(oacc[2 * dg + 1], a, vf1 + 2);
                }
            }
        }
        __syncthreads();
    }

    for (int ww = 0; ww < 4; ww++) {
        if (wq == ww) {
            #pragma unroll
            for (int t = 0; t < 16; t++) {
                int dbase = 8 * t + 2 * (lane & 3);
                int rb = gq * 16;
                num[(rb + r0) * 128 + dbase + 0] += oacc[t][0];
                num[(rb + r0) * 128 + dbase + 1] += oacc[t][1];
                num[(rb + r1) * 128 + dbase + 0] += oacc[t][2];
                num[(rb + r1) * 128 + dbase + 1] += oacc[t][3];
            }
        }
        __syncthreads();
    }
    for (int r = 0; r < 16; r += 2) {
        int rr = r + (g_tid >> 6);
        int e = (g_tid & 63) * 2;
        int qrow = gq * 16 + rr;
        float dv = den[qrow];
        float vx = num[qrow * 128 + e] / dv;
        float vy = num[qrow * 128 + e + 1] / dv;
        split_store(out0, out1, ((size_t)(b * S_ + s0 + qrow)) * H_ + head * HD_ + e, vx, vy);
    }
}

// ---- host ----
static __nv_bfloat16 *s_A0, *s_A1, *s_B0, *s_B1, *s_W0, *s_W1, *s_at0, *s_at1;
static float* s_qkvb;

static inline void cvt2(const float* A, __nv_bfloat16* d0, __nv_bfloat16* d1, int n) {
    cvt_split2_kernel<<<(n / 4 + 255) / 256, 256>>>(A, d0, d1, n);
}
static inline void gemm_go(const __nv_bfloat16* A0, const __nv_bfloat16* A1,
                           const float* bias, const float* res,
                           float* C, __nv_bfloat16* o0, __nv_bfloat16* o1,
                           int M, int K, int N, int act, int hi) {
    dim3 grid(N / 128, (M + 127) / 128);
    if (hi)
        gemm_tc_kernel<4><<<grid, 256, GSMEM>>>(A0, A1, s_W0, s_W1, bias, res, C, o0, o1, M, K, N, act);
    else
        gemm_tc_kernel<3><<<grid, 256, GSMEM>>>(A0, A1, s_W0, s_W1, bias, res, C, o0, o1, M, K, N, act);
}
static inline void run_gemm(const __nv_bfloat16* A0, const __nv_bfloat16* A1,
                            const float* W, const float* bias, const float* res,
                            float* C, __nv_bfloat16* o0, __nv_bfloat16* o1,
                            int M, int K, int N, int act, int hi) {
    cvt_t2_kernel<<<dim3(N / 32, K / 32), dim3(32, 8)>>>(W, s_W0, s_W1, K, N);
    gemm_go(A0, A1, bias, res, C, o0, o1, M, K, N, act, hi);
}

extern "C" void kernel_launch(void* const* d_in, const int* in_sizes, int n_in,
                              void* d_out, int out_size) {
    const int*   ids     = (const int*)  d_in[0];
    const float* tok_emb = (const float*)d_in[1];
    const float* pos_emb = (const float*)d_in[2];
    const float* in_w    = (const float*)d_in[3];
    const float* in_b    = (const float*)d_in[4];
    const float* ch_w1   = (const float*)d_in[5];
    const float* ch_b1   = (const float*)d_in[6];
    const float* ch_w2   = (const float*)d_in[7];
    const float* ch_b2   = (const float*)d_in[8];
    const float* qe_w1   = (const float*)d_in[9];
    const float* qe_b1   = (const float*)d_in[10];
    const float* qe_w2   = (const float*)d_in[11];
    const float* qe_b2   = (const float*)d_in[12];
    const float* q_w     = (const float*)d_in[13];
    const float* q_b     = (const float*)d_in[14];
    const float* k_w     = (const float*)d_in[15];
    const float* k_b     = (const float*)d_in[16];
    const float* v_w     = (const float*)d_in[17];
    const float* v_b     = (const float*)d_in[18];
    const float* o_w     = (const float*)d_in[19];
    const float* o_b     = (const float*)d_in[20];
    const float* f_w1    = (const float*)d_in[21];
    const float* f_b1    = (const float*)d_in[22];
    const float* f_w2    = (const float*)d_in[23];
    const float* f_b2    = (const float*)d_in[24];
    const float* ln1_g   = (const float*)d_in[25];
    const float* ln1_b   = (const float*)d_in[26];
    const float* ln2_g   = (const float*)d_in[27];
    const float* ln2_b   = (const float*)d_in[28];
    const float* out_w   = (const float*)d_in[29];
    const float* out_b   = (const float*)d_in[30];
    float* logits = (float*)d_out;

    cudaFuncSetAttribute(gemm_tc_kernel<4>, cudaFuncAttributeMaxDynamicSharedMemorySize, GSMEM);
    cudaFuncSetAttribute(gemm_tc_kernel<3>, cudaFuncAttributeMaxDynamicSharedMemorySize, GSMEM);
    cudaFuncSetAttribute(attn_kernel, cudaFuncAttributeMaxDynamicSharedMemorySize, ASMEM);

    float *h, *x, *avg, *cenc;
    unsigned* sel;
    cudaGetSymbolAddress((void**)&h,    g_h);
    cudaGetSymbolAddress((void**)&x,    g_x);
    cudaGetSymbolAddress((void**)&avg,  g_avg);
    cudaGetSymbolAddress((void**)&cenc, g_cenc);
    cudaGetSymbolAddress((void**)&sel,  g_sel);
    cudaGetSymbolAddress((void**)&s_A0, g_A0);
    cudaGetSymbolAddress((void**)&s_A1, g_A1);
    cudaGetSymbolAddress((void**)&s_B0, g_B0);
    cudaGetSymbolAddress((void**)&s_B1, g_B1);
    cudaGetSymbolAddress((void**)&s_W0, g_W0);
    cudaGetSymbolAddress((void**)&s_W1, g_W1);
    cudaGetSymbolAddress((void**)&s_at0, g_at0);
    cudaGetSymbolAddress((void**)&s_at1, g_at1);
    cudaGetSymbolAddress((void**)&s_qkvb, g_qkvb);

    // embeddings (split) -> in-proj -> h (fp32)
    embed_kernel<<<R_, 256>>>(ids, tok_emb, pos_emb, s_A0, s_A1);
    run_gemm(s_A0, s_A1, in_w, in_b, nullptr, h, nullptr, nullptr, R_, E_, H_, 0, 1);

    // chunk encodings
    chunk_avg_kernel<<<dim3(NC_, B_, 4), 256>>>(h, ids, avg);
    cvt2(avg, s_A0, s_A1, B_ * NC_ * H_);
    run_gemm(s_A0, s_A1, ch_w1, ch_b1, nullptr, nullptr, s_B0, s_B1, B_ * NC_, H_, HH_, 1, 1);
    run_gemm(s_B0, s_B1, ch_w2, ch_b2, nullptr, cenc, nullptr, nullptr, B_ * NC_, HH_, H_, 0, 1);

    for (int i = 0; i < L_; i++) {
        // selection path (hi precision)
        cvt2(h, s_A0, s_A1, R_ * H_);
        run_gemm(s_A0, s_A1, qe_w1, qe_b1, nullptr, nullptr, s_B0, s_B1, R_, H_, HH_, 1, 1);
        run_gemm(s_B0, s_B1, qe_w2, qe_b2, nullptr, x, nullptr, nullptr, R_, HH_, H_, 0, 1);
        topk_kernel<<<dim3(S_, B_), 512>>>(x, cenc, sel);

        int hi = (i == 0) ? 1 : 0;
        ln_kernel<<<R_, 256>>>(h, ln1_g + i * H_, ln1_b + i * H_, s_A0, s_A1);
        // merged qkv: W^T rows [q | k | v], bias concatenated
        cvt_t2_kernel<<<dim3(32, 32), dim3(32, 8)>>>(q_w + (size_t)i * H_ * H_, s_W0, s_W1, H_, H_);
        cvt_t2_kernel<<<dim3(32, 32), dim3(32, 8)>>>(k_w + (size_t)i * H_ * H_,
            s_W0 + (size_t)H_ * H_, s_W1 + (size_t)H_ * H_, H_, H_);
        cvt_t2_kernel<<<dim3(32, 32), dim3(32, 8)>>>(v_w + (size_t)i * H_ * H_,
            s_W0 + (size_t)2 * H_ * H_, s_W1 + (size_t)2 * H_ * H_, H_, H_);
        cudaMemcpyAsync(s_qkvb,        q_b + i * H_, H_ * 4, cudaMemcpyDeviceToDevice);
        cudaMemcpyAsync(s_qkvb + H_,   k_b + i * H_, H_ * 4, cudaMemcpyDeviceToDevice);
        cudaMemcpyAsync(s_qkvb + 2*H_, v_b + i * H_, H_ * 4, cudaMemcpyDeviceToDevice);
        gemm_go(s_A0, s_A1, s_qkvb, nullptr, nullptr, s_at0, s_at1, R_, H_, HS_, 0, hi);

        attn_kernel<<<dim3(S_ / 32, NH_, B_), 256, ASMEM>>>(s_at0, s_at1, sel, s_B0, s_B1);
        run_gemm(s_B0, s_B1, o_w + (size_t)i * H_ * H_, o_b + i * H_, h, h, nullptr, nullptr,
                 R_, H_, H_, 0, hi);

        ln_kernel<<<R_, 256>>>(h, ln2_g + i * H_, ln2_b + i * H_, s_A0, s_A1);
        run_gemm(s_A0, s_A1, f_w1 + (size_t)i * H_ * FF_, f_b1 + i * FF_, nullptr, nullptr,
                 s_B0, s_B1, R_, H_, FF_, 2, hi);
        run_gemm(s_B0, s_B1, f_w2 + (size_t)i * FF_ * H_, f_b2 + i * H_, h, h, nullptr, nullptr,
                 R_, FF_, H_, 0, hi);
    }

    cvt2(h, s_A0, s_A1, R_ * H_);
    run_gemm(s_A0, s_A1, out_w, out_b, nullptr, logits, nullptr, nullptr, R_, H_, V_, 0, 0);
}